// round 1
// baseline (speedup 1.0000x reference)
#include <cuda_runtime.h>
#include <math.h>

// Problem constants
constexpr int B  = 2;
constexpr int S  = 2048;
constexpr int E  = 1024;
constexpr int H  = 16;
constexpr int DH = 64;
constexpr int M_TOT = B * S;          // 4096

// Scratch (allocation-free rule: __device__ globals)
__device__ float g_Q[(size_t)B * H * S * DH];
__device__ float g_K[(size_t)B * H * S * DH];
__device__ float g_V[(size_t)B * H * S * DH];
__device__ float g_AO[(size_t)B * S * E];

// ---------------------------------------------------------------------------
// SGEMM: out = X @ W^T.  X:[M_TOT,E] row-major, W:[E,E] row-major (out col n
// uses W row n).  BM=BN=128, BK=8, 256 threads, 8x8 per thread.
// TRANS epilogue scatters out[m][n] -> dst[((b*H+h)*S+s)*DH+dd]
// with b=m/S, s=m%S, h=n/DH, dd=n%DH  (head-split + transpose fused).
// ---------------------------------------------------------------------------
template <bool TRANS>
__global__ void __launch_bounds__(256)
sgemm_wt(const float* __restrict__ X, const float* __restrict__ W,
         float* __restrict__ out)
{
    __shared__ float As[8][128];
    __shared__ float Bs[8][128];

    const int tid = threadIdx.x;
    const int bx = blockIdx.x, by = blockIdx.y;
    const int loadRow = tid >> 1;          // 0..127
    const int loadK4  = (tid & 1) << 2;    // 0 or 4
    const float* Aptr = X + (size_t)(by * 128 + loadRow) * E + loadK4;
    const float* Bptr = W + (size_t)(bx * 128 + loadRow) * E + loadK4;
    const int ty = tid >> 4, tx = tid & 15;

    float acc[8][8];
#pragma unroll
    for (int i = 0; i < 8; i++)
#pragma unroll
        for (int j = 0; j < 8; j++) acc[i][j] = 0.f;

    for (int k0 = 0; k0 < E; k0 += 8) {
        float4 a = *reinterpret_cast<const float4*>(Aptr + k0);
        float4 b = *reinterpret_cast<const float4*>(Bptr + k0);
        __syncthreads();
        As[loadK4 + 0][loadRow] = a.x;
        As[loadK4 + 1][loadRow] = a.y;
        As[loadK4 + 2][loadRow] = a.z;
        As[loadK4 + 3][loadRow] = a.w;
        Bs[loadK4 + 0][loadRow] = b.x;
        Bs[loadK4 + 1][loadRow] = b.y;
        Bs[loadK4 + 2][loadRow] = b.z;
        Bs[loadK4 + 3][loadRow] = b.w;
        __syncthreads();
#pragma unroll
        for (int kk = 0; kk < 8; kk++) {
            float4 a0 = *reinterpret_cast<const float4*>(&As[kk][ty * 8]);
            float4 a1 = *reinterpret_cast<const float4*>(&As[kk][ty * 8 + 4]);
            float4 b0 = *reinterpret_cast<const float4*>(&Bs[kk][tx * 8]);
            float4 b1 = *reinterpret_cast<const float4*>(&Bs[kk][tx * 8 + 4]);
            float av[8] = {a0.x, a0.y, a0.z, a0.w, a1.x, a1.y, a1.z, a1.w};
            float bv[8] = {b0.x, b0.y, b0.z, b0.w, b1.x, b1.y, b1.z, b1.w};
#pragma unroll
            for (int i = 0; i < 8; i++)
#pragma unroll
                for (int j = 0; j < 8; j++) acc[i][j] += av[i] * bv[j];
        }
    }

    const int n0 = bx * 128 + tx * 8;
#pragma unroll
    for (int i = 0; i < 8; i++) {
        const int m = by * 128 + ty * 8 + i;
        float4 s0 = make_float4(acc[i][0], acc[i][1], acc[i][2], acc[i][3]);
        float4 s1 = make_float4(acc[i][4], acc[i][5], acc[i][6], acc[i][7]);
        if (TRANS) {
            const int bb = m >> 11;       // / S
            const int ss = m & (S - 1);
            const int hh = n0 >> 6;       // / DH  (8 cols never cross a head)
            const int dd = n0 & 63;
            float* dst = out + (((size_t)bb * H + hh) * S + ss) * DH + dd;
            *reinterpret_cast<float4*>(dst)     = s0;
            *reinterpret_cast<float4*>(dst + 4) = s1;
        } else {
            float* dst = out + (size_t)m * E + n0;
            *reinterpret_cast<float4*>(dst)     = s0;
            *reinterpret_cast<float4*>(dst + 4) = s1;
        }
    }
}

// ---------------------------------------------------------------------------
// RoPE (in-place on [B*H, S, DH]).  Mirrors the reference's fp32 arithmetic:
// inv_freq rounded to fp32, pos*inv_freq in fp32, then accurate sincosf.
// ---------------------------------------------------------------------------
__global__ void rope_kernel(float* __restrict__ x)
{
    constexpr int NP = B * H * S * (DH / 2);   // 2,097,152
    const int idx = blockIdx.x * blockDim.x + threadIdx.x;
    if (idx >= NP) return;
    const int i  = idx & 31;            // pair index 0..31
    const int s  = (idx >> 5) & (S - 1);
    const int bh = idx >> 16;           // / (32*S)

    const float inv_freq = (float)pow(10000.0, -(double)(2 * i) / 64.0);
    const float ang = (float)s * inv_freq;
    float sn, cs;
    sincosf(ang, &sn, &cs);

    float2* p = reinterpret_cast<float2*>(x + (((size_t)bh * S + s) * DH) + 2 * i);
    float2 v = *p;
    const float xe = v.x, xo = v.y;
    v.x = xe * cs - xo * sn;
    v.y = xo * cs + xe * sn;
    *p = v;
}

// ---------------------------------------------------------------------------
// fp32 flash attention (non-causal).  Grid: (S/64, H, B), 256 threads.
// 64-query tile, 64-key tiles, 4x4 register microtiles, online softmax.
// smem: Qt[64][68] (k-major, padded), Kt[64][68], V[64][64], P[64][64].
// ---------------------------------------------------------------------------
__global__ void __launch_bounds__(256)
flash_attn(const float* __restrict__ Q, const float* __restrict__ Kg,
           const float* __restrict__ Vg, float* __restrict__ AO)
{
    extern __shared__ float sm[];
    float* sQt = sm;                       // 64*68
    float* sKt = sm + 64 * 68;             // 64*68
    float* sV  = sm + 2 * 64 * 68;         // 64*64
    float* sP  = sm + 2 * 64 * 68 + 64 * 64; // 64*64

    const int tid = threadIdx.x;
    const int tx = tid & 15, ty = tid >> 4;
    const int q0 = blockIdx.x * 64;
    const int hh = blockIdx.y;
    const int bb = blockIdx.z;
    const int bh = bb * H + hh;
    const size_t qbase = ((size_t)bh * S + q0) * DH;

    // load Q tile transposed (k-major, pitch 68)
#pragma unroll
    for (int rep = 0; rep < 4; rep++) {
        const int idx = rep * 256 + tid;
        const int r  = idx >> 4;
        const int c4 = (idx & 15) << 2;
        float4 v = *reinterpret_cast<const float4*>(Q + qbase + r * 64 + c4);
        sQt[(c4 + 0) * 68 + r] = v.x;
        sQt[(c4 + 1) * 68 + r] = v.y;
        sQt[(c4 + 2) * 68 + r] = v.z;
        sQt[(c4 + 3) * 68 + r] = v.w;
    }

    float m_run[4], l_run[4], o[4][4];
#pragma unroll
    for (int i = 0; i < 4; i++) {
        m_run[i] = -1e30f;
        l_run[i] = 0.f;
#pragma unroll
        for (int j = 0; j < 4; j++) o[i][j] = 0.f;
    }

    for (int t = 0; t < S / 64; t++) {
        const size_t kbase = ((size_t)bh * S + t * 64) * DH;
        __syncthreads();   // previous tile fully consumed
#pragma unroll
        for (int rep = 0; rep < 4; rep++) {
            const int idx = rep * 256 + tid;
            const int r  = idx >> 4;
            const int c4 = (idx & 15) << 2;
            float4 kv = *reinterpret_cast<const float4*>(Kg + kbase + r * 64 + c4);
            sKt[(c4 + 0) * 68 + r] = kv.x;
            sKt[(c4 + 1) * 68 + r] = kv.y;
            sKt[(c4 + 2) * 68 + r] = kv.z;
            sKt[(c4 + 3) * 68 + r] = kv.w;
            float4 vv = *reinterpret_cast<const float4*>(Vg + kbase + r * 64 + c4);
            *reinterpret_cast<float4*>(&sV[r * 64 + c4]) = vv;
        }
        __syncthreads();

        // S = Q K^T
        float accS[4][4];
#pragma unroll
        for (int i = 0; i < 4; i++)
#pragma unroll
            for (int j = 0; j < 4; j++) accS[i][j] = 0.f;

#pragma unroll 8
        for (int kk = 0; kk < 64; kk++) {
            float4 qa = *reinterpret_cast<const float4*>(&sQt[kk * 68 + ty * 4]);
            float4 kb = *reinterpret_cast<const float4*>(&sKt[kk * 68 + tx * 4]);
            float av[4] = {qa.x, qa.y, qa.z, qa.w};
            float bv[4] = {kb.x, kb.y, kb.z, kb.w};
#pragma unroll
            for (int i = 0; i < 4; i++)
#pragma unroll
                for (int j = 0; j < 4; j++) accS[i][j] += av[i] * bv[j];
        }

        // online softmax (scale = 1/sqrt(E) = 0.03125)
#pragma unroll
        for (int i = 0; i < 4; i++) {
            const float s0 = accS[i][0] * 0.03125f;
            const float s1 = accS[i][1] * 0.03125f;
            const float s2 = accS[i][2] * 0.03125f;
            const float s3 = accS[i][3] * 0.03125f;
            float mx = fmaxf(fmaxf(s0, s1), fmaxf(s2, s3));
#pragma unroll
            for (int off = 8; off > 0; off >>= 1)
                mx = fmaxf(mx, __shfl_xor_sync(0xffffffffu, mx, off));
            const float newm = fmaxf(m_run[i], mx);
            const float corr = __expf(m_run[i] - newm);
            m_run[i] = newm;
            const float p0 = __expf(s0 - newm);
            const float p1 = __expf(s1 - newm);
            const float p2 = __expf(s2 - newm);
            const float p3 = __expf(s3 - newm);
            float ls = p0 + p1 + p2 + p3;
#pragma unroll
            for (int off = 8; off > 0; off >>= 1)
                ls += __shfl_xor_sync(0xffffffffu, ls, off);
            l_run[i] = l_run[i] * corr + ls;
#pragma unroll
            for (int j = 0; j < 4; j++) o[i][j] *= corr;
            *reinterpret_cast<float4*>(&sP[(ty * 4 + i) * 64 + tx * 4]) =
                make_float4(p0, p1, p2, p3);
        }
        __syncthreads();

        // O += P @ V
#pragma unroll 4
        for (int j = 0; j < 64; j++) {
            float4 vv = *reinterpret_cast<const float4*>(&sV[j * 64 + tx * 4]);
            const float pr0 = sP[(ty * 4 + 0) * 64 + j];
            const float pr1 = sP[(ty * 4 + 1) * 64 + j];
            const float pr2 = sP[(ty * 4 + 2) * 64 + j];
            const float pr3 = sP[(ty * 4 + 3) * 64 + j];
            o[0][0] += pr0 * vv.x; o[0][1] += pr0 * vv.y; o[0][2] += pr0 * vv.z; o[0][3] += pr0 * vv.w;
            o[1][0] += pr1 * vv.x; o[1][1] += pr1 * vv.y; o[1][2] += pr1 * vv.z; o[1][3] += pr1 * vv.w;
            o[2][0] += pr2 * vv.x; o[2][1] += pr2 * vv.y; o[2][2] += pr2 * vv.z; o[2][3] += pr2 * vv.w;
            o[3][0] += pr3 * vv.x; o[3][1] += pr3 * vv.y; o[3][2] += pr3 * vv.z; o[3][3] += pr3 * vv.w;
        }
    }

    // write back to [B, S, E] layout for the output projection
#pragma unroll
    for (int i = 0; i < 4; i++) {
        const float inv = 1.f / l_run[i];
        const int row = q0 + ty * 4 + i;
        float4 st = make_float4(o[i][0] * inv, o[i][1] * inv,
                                o[i][2] * inv, o[i][3] * inv);
        *reinterpret_cast<float4*>(
            &AO[((size_t)bb * S + row) * E + hh * 64 + tx * 4]) = st;
    }
}

// ---------------------------------------------------------------------------
extern "C" void kernel_launch(void* const* d_in, const int* in_sizes, int n_in,
                              void* d_out, int out_size)
{
    const float* q  = (const float*)d_in[0];
    const float* k  = (const float*)d_in[1];
    const float* v  = (const float*)d_in[2];
    const float* Wq = (const float*)d_in[3];
    const float* Wk = (const float*)d_in[4];
    const float* Wv = (const float*)d_in[5];
    const float* Wo = (const float*)d_in[6];
    float* out = (float*)d_out;

    float *pQ, *pK, *pV, *pAO;
    cudaGetSymbolAddress((void**)&pQ,  g_Q);
    cudaGetSymbolAddress((void**)&pK,  g_K);
    cudaGetSymbolAddress((void**)&pV,  g_V);
    cudaGetSymbolAddress((void**)&pAO, g_AO);

    constexpr int SMEM_ATTN = (2 * 64 * 68 + 2 * 64 * 64) * 4;  // 67584 B
    cudaFuncSetAttribute(flash_attn,
                         cudaFuncAttributeMaxDynamicSharedMemorySize, SMEM_ATTN);

    dim3 gg(E / 128, M_TOT / 128);   // (8, 32)
    sgemm_wt<true><<<gg, 256>>>(q, Wq, pQ);
    sgemm_wt<true><<<gg, 256>>>(k, Wk, pK);
    sgemm_wt<true><<<gg, 256>>>(v, Wv, pV);

    constexpr int NP = B * H * S * (DH / 2);
    rope_kernel<<<(NP + 255) / 256, 256>>>(pQ);
    rope_kernel<<<(NP + 255) / 256, 256>>>(pK);

    dim3 ag(S / 64, H, B);
    flash_attn<<<ag, 256, SMEM_ATTN>>>(pQ, pK, pV, pAO);

    sgemm_wt<false><<<gg, 256>>>(pAO, Wo, out);
}

// round 2
// speedup vs baseline: 1.3153x; 1.3153x over previous
#include <cuda_runtime.h>
#include <math.h>

// Problem constants
constexpr int B  = 2;
constexpr int S  = 2048;
constexpr int E  = 1024;
constexpr int H  = 16;
constexpr int DH = 64;
constexpr int M_TOT = B * S;          // 4096

// Scratch (allocation-free rule: __device__ globals)
__device__ float g_Q[(size_t)B * H * S * DH];
__device__ float g_K[(size_t)B * H * S * DH];
__device__ float g_V[(size_t)B * H * S * DH];
__device__ float g_AO[(size_t)B * S * E];
__device__ float g_invfreq[32];

// ---------------------------------------------------------------------------
// One-time-per-call tiny init: fp64 pow done by 32 threads total (was: 2M!)
// ---------------------------------------------------------------------------
__global__ void init_invfreq_kernel()
{
    const int i = threadIdx.x;
    g_invfreq[i] = (float)pow(10000.0, -(double)(2 * i) / 64.0);
}

// ---------------------------------------------------------------------------
// SGEMM: out = X @ W^T.  BM=BN=128, BK=16, 256 threads, 8x8 per thread.
// TRANS epilogue scatters into [B,H,S,DH] (head split + transpose fused).
// ---------------------------------------------------------------------------
template <bool TRANS>
__global__ void __launch_bounds__(256)
sgemm_wt(const float* __restrict__ X, const float* __restrict__ W,
         float* __restrict__ out)
{
    __shared__ float As[16][128];
    __shared__ float Bs[16][128];

    const int tid = threadIdx.x;
    const int bx = blockIdx.x, by = blockIdx.y;
    const int loadRow = tid >> 1;          // 0..127
    const int loadK   = (tid & 1) << 3;    // 0 or 8
    const float* Aptr = X + (size_t)(by * 128 + loadRow) * E + loadK;
    const float* Bptr = W + (size_t)(bx * 128 + loadRow) * E + loadK;
    const int ty = tid >> 4, tx = tid & 15;

    float acc[8][8];
#pragma unroll
    for (int i = 0; i < 8; i++)
#pragma unroll
        for (int j = 0; j < 8; j++) acc[i][j] = 0.f;

    for (int k0 = 0; k0 < E; k0 += 16) {
        float4 a0 = *reinterpret_cast<const float4*>(Aptr + k0);
        float4 a1 = *reinterpret_cast<const float4*>(Aptr + k0 + 4);
        float4 b0 = *reinterpret_cast<const float4*>(Bptr + k0);
        float4 b1 = *reinterpret_cast<const float4*>(Bptr + k0 + 4);
        __syncthreads();
        As[loadK + 0][loadRow] = a0.x; As[loadK + 1][loadRow] = a0.y;
        As[loadK + 2][loadRow] = a0.z; As[loadK + 3][loadRow] = a0.w;
        As[loadK + 4][loadRow] = a1.x; As[loadK + 5][loadRow] = a1.y;
        As[loadK + 6][loadRow] = a1.z; As[loadK + 7][loadRow] = a1.w;
        Bs[loadK + 0][loadRow] = b0.x; Bs[loadK + 1][loadRow] = b0.y;
        Bs[loadK + 2][loadRow] = b0.z; Bs[loadK + 3][loadRow] = b0.w;
        Bs[loadK + 4][loadRow] = b1.x; Bs[loadK + 5][loadRow] = b1.y;
        Bs[loadK + 6][loadRow] = b1.z; Bs[loadK + 7][loadRow] = b1.w;
        __syncthreads();
#pragma unroll
        for (int kk = 0; kk < 16; kk++) {
            float4 av0 = *reinterpret_cast<const float4*>(&As[kk][ty * 8]);
            float4 av1 = *reinterpret_cast<const float4*>(&As[kk][ty * 8 + 4]);
            float4 bv0 = *reinterpret_cast<const float4*>(&Bs[kk][tx * 8]);
            float4 bv1 = *reinterpret_cast<const float4*>(&Bs[kk][tx * 8 + 4]);
            float av[8] = {av0.x, av0.y, av0.z, av0.w, av1.x, av1.y, av1.z, av1.w};
            float bv[8] = {bv0.x, bv0.y, bv0.z, bv0.w, bv1.x, bv1.y, bv1.z, bv1.w};
#pragma unroll
            for (int i = 0; i < 8; i++)
#pragma unroll
                for (int j = 0; j < 8; j++) acc[i][j] += av[i] * bv[j];
        }
    }

    const int n0 = bx * 128 + tx * 8;
#pragma unroll
    for (int i = 0; i < 8; i++) {
        const int m = by * 128 + ty * 8 + i;
        float4 s0 = make_float4(acc[i][0], acc[i][1], acc[i][2], acc[i][3]);
        float4 s1 = make_float4(acc[i][4], acc[i][5], acc[i][6], acc[i][7]);
        if (TRANS) {
            const int bb = m >> 11;
            const int ss = m & (S - 1);
            const int hh = n0 >> 6;
            const int dd = n0 & 63;
            float* dst = out + (((size_t)bb * H + hh) * S + ss) * DH + dd;
            *reinterpret_cast<float4*>(dst)     = s0;
            *reinterpret_cast<float4*>(dst + 4) = s1;
        } else {
            float* dst = out + (size_t)m * E + n0;
            *reinterpret_cast<float4*>(dst)     = s0;
            *reinterpret_cast<float4*>(dst + 4) = s1;
        }
    }
}

// ---------------------------------------------------------------------------
// RoPE (in-place on [B*H, S, DH]); inv_freq from precomputed table.
// scale (power of two) folded into the rotated value — exact.
// ---------------------------------------------------------------------------
__global__ void rope_kernel(float* __restrict__ x, float scale)
{
    constexpr int NP = B * H * S * (DH / 2);
    const int idx = blockIdx.x * blockDim.x + threadIdx.x;
    if (idx >= NP) return;
    const int i  = idx & 31;
    const int s  = (idx >> 5) & (S - 1);
    const int bh = idx >> 16;

    const float inv_freq = g_invfreq[i];
    const float ang = (float)s * inv_freq;
    float sn, cs;
    sincosf(ang, &sn, &cs);

    float2* p = reinterpret_cast<float2*>(x + (((size_t)bh * S + s) * DH) + 2 * i);
    float2 v = *p;
    const float xe = v.x, xo = v.y;
    v.x = (xe * cs - xo * sn) * scale;
    v.y = (xo * cs + xe * sn) * scale;
    *p = v;
}

// ---------------------------------------------------------------------------
// fp32 flash attention v2 (non-causal). Grid: (S/64, H, B), 256 threads.
// 64-query x 128-key tiles. QK: 4x8 microtile (16x16 thread grid) with
// XOR-swizzled K smem. PV: 2x8 microtile (32x8 grid), even/odd split V.
// P aliases the K buffer. Per-row softmax state in smem bridges remaps.
// Q arrives pre-scaled by 1/sqrt(E).
// ---------------------------------------------------------------------------
constexpr int FL_SQ   = 0;                 // [64][64]
constexpr int FL_SKP  = 64 * 64;           // K [128][64] swizzled / P [64][132]
constexpr int FL_SV   = FL_SKP + 64 * 132; // [128][64] even/odd split
constexpr int FL_SM   = FL_SV + 128 * 64;  // [64]
constexpr int FL_SL   = FL_SM + 64;        // [64]
constexpr int FL_SC   = FL_SL + 64;        // [64]
constexpr int FL_FLOATS = FL_SC + 64;
constexpr int FL_SMEM = FL_FLOATS * 4;     // 83712 B

__global__ void __launch_bounds__(256, 2)
flash_attn(const float* __restrict__ Q, const float* __restrict__ Kg,
           const float* __restrict__ Vg, float* __restrict__ AO)
{
    extern __shared__ float sm[];
    float* sQ  = sm + FL_SQ;
    float* sKP = sm + FL_SKP;
    float* sV  = sm + FL_SV;
    float* sM  = sm + FL_SM;
    float* sL  = sm + FL_SL;
    float* sC  = sm + FL_SC;

    const int tid = threadIdx.x;
    const int txk = tid & 15, tyk = tid >> 4;   // QK map: 4 rows x 8 cols
    const int txv = tid & 7,  tyv = tid >> 3;   // PV map: 2 rows x 8 cols
    const int q0 = blockIdx.x * 64;
    const int bh = blockIdx.z * H + blockIdx.y;
    const size_t qgbase = ((size_t)bh * S + q0) * DH;

    // load Q tile (row-major [64][64], reads are half-warp broadcasts)
#pragma unroll
    for (int rep = 0; rep < 4; rep++) {
        const int idx = rep * 256 + tid;
        const int r  = idx >> 4;
        const int c4 = (idx & 15) << 2;
        *reinterpret_cast<float4*>(&sQ[r * 64 + c4]) =
            *reinterpret_cast<const float4*>(Q + qgbase + r * 64 + c4);
    }
    if (tid < 64) { sM[tid] = -1e30f; sL[tid] = 0.f; }

    float o[2][8];
#pragma unroll
    for (int r = 0; r < 2; r++)
#pragma unroll
        for (int c = 0; c < 8; c++) o[r][c] = 0.f;

    for (int t = 0; t < S / 128; t++) {
        const size_t kgbase = ((size_t)bh * S + t * 128) * DH;
        __syncthreads();   // prior tile's P/V reads complete
        // load K (swizzled: float4-group ^= key>>3) and V (even/odd split)
#pragma unroll
        for (int rep = 0; rep < 8; rep++) {
            const int idx = rep * 256 + tid;
            const int r  = idx >> 4;            // key 0..127
            const int c4 = (idx & 15) << 2;
            float4 kv = *reinterpret_cast<const float4*>(Kg + kgbase + r * 64 + c4);
            const int ksw = (((c4 >> 2) ^ (r >> 3)) & 15) << 2;
            *reinterpret_cast<float4*>(&sKP[r * 64 + ksw]) = kv;
            float4 vv = *reinterpret_cast<const float4*>(Vg + kgbase + r * 64 + c4);
            const int g = c4 >> 2;
            const int vp = ((g & 1) << 5) + ((g >> 1) << 2);
            *reinterpret_cast<float4*>(&sV[r * 64 + vp]) = vv;
        }
        __syncthreads();

        // ---- S = Q K^T : acc[4 rows][8 cols] ----
        float acc[4][8];
#pragma unroll
        for (int i = 0; i < 4; i++)
#pragma unroll
            for (int j = 0; j < 8; j++) acc[i][j] = 0.f;

        const float* kbase = &sKP[(txk * 8) * 64];
#pragma unroll
        for (int kg = 0; kg < 16; kg++) {
            float4 qv[4];
#pragma unroll
            for (int i = 0; i < 4; i++)
                qv[i] = *reinterpret_cast<const float4*>(&sQ[(tyk * 4 + i) * 64 + kg * 4]);
            const int kcol = ((kg ^ txk) & 15) << 2;   // key>>3 == txk here
#pragma unroll
            for (int jh = 0; jh < 2; jh++) {
                float4 kv[4];
#pragma unroll
                for (int jj = 0; jj < 4; jj++)
                    kv[jj] = *reinterpret_cast<const float4*>(&kbase[(jh * 4 + jj) * 64 + kcol]);
#pragma unroll
                for (int i = 0; i < 4; i++)
#pragma unroll
                    for (int jj = 0; jj < 4; jj++) {
                        const int j = jh * 4 + jj;
                        acc[i][j] += qv[i].x * kv[jj].x;
                        acc[i][j] += qv[i].y * kv[jj].y;
                        acc[i][j] += qv[i].z * kv[jj].z;
                        acc[i][j] += qv[i].w * kv[jj].w;
                    }
            }
        }

        // ---- online softmax (rows tyk*4+i, 16 threads per row) ----
#pragma unroll
        for (int i = 0; i < 4; i++) {
            const int row = tyk * 4 + i;
            float mx = acc[i][0];
#pragma unroll
            for (int j = 1; j < 8; j++) mx = fmaxf(mx, acc[i][j]);
#pragma unroll
            for (int off = 8; off > 0; off >>= 1)
                mx = fmaxf(mx, __shfl_xor_sync(0xffffffffu, mx, off));
            const float oldm = sM[row];
            const float newm = fmaxf(oldm, mx);
            float ls = 0.f;
#pragma unroll
            for (int j = 0; j < 8; j++) {
                acc[i][j] = __expf(acc[i][j] - newm);
                ls += acc[i][j];
            }
#pragma unroll
            for (int off = 8; off > 0; off >>= 1)
                ls += __shfl_xor_sync(0xffffffffu, ls, off);
            if (txk == 0) {
                const float corr = __expf(oldm - newm);
                sM[row] = newm;
                sC[row] = corr;
                sL[row] = sL[row] * corr + ls;
            }
        }
        __syncthreads();   // all QK reads of sKP done -> safe to overwrite with P

        // store P row-major [64][132]
#pragma unroll
        for (int i = 0; i < 4; i++) {
            const int row = tyk * 4 + i;
            *reinterpret_cast<float4*>(&sKP[row * 132 + txk * 8]) =
                make_float4(acc[i][0], acc[i][1], acc[i][2], acc[i][3]);
            *reinterpret_cast<float4*>(&sKP[row * 132 + txk * 8 + 4]) =
                make_float4(acc[i][4], acc[i][5], acc[i][6], acc[i][7]);
        }
        __syncthreads();

        // ---- O += P V : o[2 rows][8 cols] ----
        const int r0 = tyv * 2;
        const float c0 = sC[r0], c1 = sC[r0 + 1];
#pragma unroll
        for (int c = 0; c < 8; c++) { o[0][c] *= c0; o[1][c] *= c1; }

#pragma unroll 4
        for (int j4 = 0; j4 < 32; j4++) {
            float4 p0 = *reinterpret_cast<const float4*>(&sKP[r0 * 132 + j4 * 4]);
            float4 p1 = *reinterpret_cast<const float4*>(&sKP[(r0 + 1) * 132 + j4 * 4]);
            float pr0[4] = {p0.x, p0.y, p0.z, p0.w};
            float pr1[4] = {p1.x, p1.y, p1.z, p1.w};
#pragma unroll
            for (int jj = 0; jj < 4; jj++) {
                const int j = j4 * 4 + jj;
                float4 v0 = *reinterpret_cast<const float4*>(&sV[j * 64 + txv * 4]);
                float4 v1 = *reinterpret_cast<const float4*>(&sV[j * 64 + 32 + txv * 4]);
                o[0][0] += pr0[jj] * v0.x; o[0][1] += pr0[jj] * v0.y;
                o[0][2] += pr0[jj] * v0.z; o[0][3] += pr0[jj] * v0.w;
                o[0][4] += pr0[jj] * v1.x; o[0][5] += pr0[jj] * v1.y;
                o[0][6] += pr0[jj] * v1.z; o[0][7] += pr0[jj] * v1.w;
                o[1][0] += pr1[jj] * v0.x; o[1][1] += pr1[jj] * v0.y;
                o[1][2] += pr1[jj] * v0.z; o[1][3] += pr1[jj] * v0.w;
                o[1][4] += pr1[jj] * v1.x; o[1][5] += pr1[jj] * v1.y;
                o[1][6] += pr1[jj] * v1.z; o[1][7] += pr1[jj] * v1.w;
            }
        }
    }

    // epilogue: normalize + write [B, S, E] for the output projection
    const int r0 = tyv * 2;
    const float inv0 = 1.f / sL[r0];
    const float inv1 = 1.f / sL[r0 + 1];
    float* d0 = &AO[((size_t)blockIdx.z * S + q0 + r0) * E + blockIdx.y * 64 + txv * 8];
    float* d1 = d0 + E;
    *reinterpret_cast<float4*>(d0) =
        make_float4(o[0][0] * inv0, o[0][1] * inv0, o[0][2] * inv0, o[0][3] * inv0);
    *reinterpret_cast<float4*>(d0 + 4) =
        make_float4(o[0][4] * inv0, o[0][5] * inv0, o[0][6] * inv0, o[0][7] * inv0);
    *reinterpret_cast<float4*>(d1) =
        make_float4(o[1][0] * inv1, o[1][1] * inv1, o[1][2] * inv1, o[1][3] * inv1);
    *reinterpret_cast<float4*>(d1 + 4) =
        make_float4(o[1][4] * inv1, o[1][5] * inv1, o[1][6] * inv1, o[1][7] * inv1);
}

// ---------------------------------------------------------------------------
extern "C" void kernel_launch(void* const* d_in, const int* in_sizes, int n_in,
                              void* d_out, int out_size)
{
    const float* q  = (const float*)d_in[0];
    const float* k  = (const float*)d_in[1];
    const float* v  = (const float*)d_in[2];
    const float* Wq = (const float*)d_in[3];
    const float* Wk = (const float*)d_in[4];
    const float* Wv = (const float*)d_in[5];
    const float* Wo = (const float*)d_in[6];
    float* out = (float*)d_out;

    float *pQ, *pK, *pV, *pAO;
    cudaGetSymbolAddress((void**)&pQ,  g_Q);
    cudaGetSymbolAddress((void**)&pK,  g_K);
    cudaGetSymbolAddress((void**)&pV,  g_V);
    cudaGetSymbolAddress((void**)&pAO, g_AO);

    cudaFuncSetAttribute(flash_attn,
                         cudaFuncAttributeMaxDynamicSharedMemorySize, FL_SMEM);

    init_invfreq_kernel<<<1, 32>>>();

    dim3 gg(E / 128, M_TOT / 128);   // (8, 32)
    sgemm_wt<true><<<gg, 256>>>(q, Wq, pQ);
    sgemm_wt<true><<<gg, 256>>>(k, Wk, pK);
    sgemm_wt<true><<<gg, 256>>>(v, Wv, pV);

    constexpr int NP = B * H * S * (DH / 2);
    rope_kernel<<<(NP + 255) / 256, 256>>>(pQ, 0.03125f);  // fold 1/sqrt(E), exact
    rope_kernel<<<(NP + 255) / 256, 256>>>(pK, 1.0f);

    dim3 ag(S / 64, H, B);
    flash_attn<<<ag, 256, FL_SMEM>>>(pQ, pK, pV, pAO);

    sgemm_wt<false><<<gg, 256>>>(pAO, Wo, out);
}

// round 3
// speedup vs baseline: 1.7331x; 1.3177x over previous
#include <cuda_runtime.h>
#include <cuda_bf16.h>
#include <math.h>
#include <stdint.h>

// Problem constants
constexpr int B  = 2;
constexpr int S  = 2048;
constexpr int E  = 1024;
constexpr int H  = 16;
constexpr int DH = 64;
constexpr int M_TOT = B * S;          // 4096

// Scratch (allocation-free rule: __device__ globals)
__device__ float g_Q[(size_t)B * H * S * DH];
__device__ float g_K[(size_t)B * H * S * DH];
__device__ float g_V[(size_t)B * H * S * DH];
__device__ float g_AO[(size_t)B * S * E];
__device__ float g_invfreq[32];
// bf16 hi/lo split buffers (reused across the 4 sequential GEMMs)
__device__ __nv_bfloat16 g_aH[(size_t)M_TOT * E];
__device__ __nv_bfloat16 g_aL[(size_t)M_TOT * E];
__device__ __nv_bfloat16 g_wH[(size_t)E * E];
__device__ __nv_bfloat16 g_wL[(size_t)E * E];

// ---------------------------------------------------------------------------
__global__ void init_invfreq_kernel()
{
    const int i = threadIdx.x;
    g_invfreq[i] = (float)pow(10000.0, -(double)(2 * i) / 64.0);
}

// ---------------------------------------------------------------------------
// fp32 -> bf16 hi/lo split (x = hi + lo + O(2^-18 x))
// ---------------------------------------------------------------------------
__global__ void __launch_bounds__(256)
convert_split(const float* __restrict__ x, __nv_bfloat16* __restrict__ hi,
              __nv_bfloat16* __restrict__ lo, int n4)
{
    const int i = blockIdx.x * blockDim.x + threadIdx.x;
    if (i >= n4) return;
    float4 v = reinterpret_cast<const float4*>(x)[i];
    __nv_bfloat16 h0 = __float2bfloat16(v.x);
    __nv_bfloat16 h1 = __float2bfloat16(v.y);
    __nv_bfloat16 h2 = __float2bfloat16(v.z);
    __nv_bfloat16 h3 = __float2bfloat16(v.w);
    __nv_bfloat16 l0 = __float2bfloat16(v.x - __bfloat162float(h0));
    __nv_bfloat16 l1 = __float2bfloat16(v.y - __bfloat162float(h1));
    __nv_bfloat16 l2 = __float2bfloat16(v.z - __bfloat162float(h2));
    __nv_bfloat16 l3 = __float2bfloat16(v.w - __bfloat162float(h3));
    __nv_bfloat162 hp0{h0, h1}, hp1{h2, h3}, lp0{l0, l1}, lp1{l2, l3};
    uint2 hu, lu;
    hu.x = *reinterpret_cast<uint32_t*>(&hp0);
    hu.y = *reinterpret_cast<uint32_t*>(&hp1);
    lu.x = *reinterpret_cast<uint32_t*>(&lp0);
    lu.y = *reinterpret_cast<uint32_t*>(&lp1);
    *reinterpret_cast<uint2*>(hi + 4 * (size_t)i) = hu;
    *reinterpret_cast<uint2*>(lo + 4 * (size_t)i) = lu;
}

// ---------------------------------------------------------------------------
// Tensor-core GEMM (bf16 hi/lo split): out = A @ B^T, A:[4096,1024], B:[1024,1024]
// both K-major.  BM=BN=128, BK=32, 256 threads (8 warps, warp tile 32m x 64n),
// mma.sync.m16n8k16 bf16, 3 MMAs per tile (hh, hl, lh).
// TRANS epilogue scatters into [B,H,S,DH].
// ---------------------------------------------------------------------------
__device__ __forceinline__ uint32_t smem_u32(const void* p)
{
    uint32_t a;
    asm("{ .reg .u64 t; cvta.to.shared.u64 t, %1; cvt.u32.u64 %0, t; }"
        : "=r"(a) : "l"(p));
    return a;
}
__device__ __forceinline__ void ldsm4(uint32_t* r, uint32_t addr)
{
    asm volatile("ldmatrix.sync.aligned.m8n8.x4.shared.b16 {%0,%1,%2,%3}, [%4];"
                 : "=r"(r[0]), "=r"(r[1]), "=r"(r[2]), "=r"(r[3]) : "r"(addr));
}
__device__ __forceinline__ void mma16816(float* c, const uint32_t* a,
                                         const uint32_t* b)
{
    asm volatile("mma.sync.aligned.m16n8k16.row.col.f32.bf16.bf16.f32 "
                 "{%0,%1,%2,%3}, {%4,%5,%6,%7}, {%8,%9}, {%0,%1,%2,%3};"
                 : "+f"(c[0]), "+f"(c[1]), "+f"(c[2]), "+f"(c[3])
                 : "r"(a[0]), "r"(a[1]), "r"(a[2]), "r"(a[3]),
                   "r"(b[0]), "r"(b[1]));
}
// swizzled byte offset inside a [128 rows][32 bf16] tile (64B rows, 16B chunks)
__device__ __forceinline__ uint32_t swz(int row, int c)
{
    return (uint32_t)(row * 64 + ((c ^ ((row >> 1) & 3)) << 4));
}

template <bool TRANS>
__global__ void __launch_bounds__(256)
gemm_mma(const __nv_bfloat16* __restrict__ Ahg, const __nv_bfloat16* __restrict__ Alg,
         const __nv_bfloat16* __restrict__ Bhg, const __nv_bfloat16* __restrict__ Blg,
         float* __restrict__ out)
{
    __shared__ __align__(16) uint8_t smem[32768];
    constexpr uint32_t oAh = 0, oAl = 8192, oBh = 16384, oBl = 24576;
    const uint32_t sbase = smem_u32(smem);

    const int tid  = threadIdx.x;
    const int warp = tid >> 5, lane = tid & 31;
    const int wm = warp & 3;      // m-warp: rows wm*32
    const int wn = warp >> 2;     // n-warp: cols wn*64
    const int bx = blockIdx.x, by = blockIdx.y;

    // loader mapping: thread -> (row, 16-element half)
    const int lr = tid >> 1, lhalf = tid & 1;
    const size_t aoff = (size_t)(by * 128 + lr) * E + lhalf * 16;
    const size_t boff = (size_t)(bx * 128 + lr) * E + lhalf * 16;
    const uint32_t w0 = swz(lr, lhalf * 2);
    const uint32_t w1 = swz(lr, lhalf * 2 + 1);

    // ldmatrix addresses (relative to tile base; same for hi/lo)
    uint32_t adA[2][2], adB[4][2];
#pragma unroll
    for (int s = 0; s < 2; s++) {
#pragma unroll
        for (int mt = 0; mt < 2; mt++)
            adA[mt][s] = swz(wm * 32 + mt * 16 + (lane & 15), s * 2 + (lane >> 4));
#pragma unroll
        for (int g = 0; g < 4; g++)
            adB[g][s] = swz(wn * 64 + g * 16 + ((lane >> 1) & 8) + (lane & 7),
                            s * 2 + ((lane >> 3) & 1));
    }

    float acc[2][8][4];
#pragma unroll
    for (int mt = 0; mt < 2; mt++)
#pragma unroll
        for (int j = 0; j < 8; j++)
#pragma unroll
            for (int r = 0; r < 4; r++) acc[mt][j][r] = 0.f;

#pragma unroll 1
    for (int k0 = 0; k0 < E; k0 += 32) {
        uint4 vAh0 = *reinterpret_cast<const uint4*>(Ahg + aoff + k0);
        uint4 vAh1 = *reinterpret_cast<const uint4*>(Ahg + aoff + k0 + 8);
        uint4 vAl0 = *reinterpret_cast<const uint4*>(Alg + aoff + k0);
        uint4 vAl1 = *reinterpret_cast<const uint4*>(Alg + aoff + k0 + 8);
        uint4 vBh0 = *reinterpret_cast<const uint4*>(Bhg + boff + k0);
        uint4 vBh1 = *reinterpret_cast<const uint4*>(Bhg + boff + k0 + 8);
        uint4 vBl0 = *reinterpret_cast<const uint4*>(Blg + boff + k0);
        uint4 vBl1 = *reinterpret_cast<const uint4*>(Blg + boff + k0 + 8);
        __syncthreads();
        *reinterpret_cast<uint4*>(smem + oAh + w0) = vAh0;
        *reinterpret_cast<uint4*>(smem + oAh + w1) = vAh1;
        *reinterpret_cast<uint4*>(smem + oAl + w0) = vAl0;
        *reinterpret_cast<uint4*>(smem + oAl + w1) = vAl1;
        *reinterpret_cast<uint4*>(smem + oBh + w0) = vBh0;
        *reinterpret_cast<uint4*>(smem + oBh + w1) = vBh1;
        *reinterpret_cast<uint4*>(smem + oBl + w0) = vBl0;
        *reinterpret_cast<uint4*>(smem + oBl + w1) = vBl1;
        __syncthreads();

#pragma unroll
        for (int s = 0; s < 2; s++) {
            uint32_t fAh[2][4], fAl[2][4], fBh[4][4], fBl[4][4];
#pragma unroll
            for (int mt = 0; mt < 2; mt++) {
                ldsm4(fAh[mt], sbase + oAh + adA[mt][s]);
                ldsm4(fAl[mt], sbase + oAl + adA[mt][s]);
            }
#pragma unroll
            for (int g = 0; g < 4; g++) {
                ldsm4(fBh[g], sbase + oBh + adB[g][s]);
                ldsm4(fBl[g], sbase + oBl + adB[g][s]);
            }
#pragma unroll
            for (int mt = 0; mt < 2; mt++)
#pragma unroll
                for (int j = 0; j < 8; j++) {
                    const int g = j >> 1, p = (j & 1) * 2;
                    uint32_t bh[2] = {fBh[g][p], fBh[g][p + 1]};
                    uint32_t bl[2] = {fBl[g][p], fBl[g][p + 1]};
                    mma16816(acc[mt][j], fAh[mt], bh);
                    mma16816(acc[mt][j], fAh[mt], bl);
                    mma16816(acc[mt][j], fAl[mt], bh);
                }
        }
    }

    // epilogue
#pragma unroll
    for (int mt = 0; mt < 2; mt++)
#pragma unroll
        for (int j = 0; j < 8; j++) {
            const int m0 = by * 128 + wm * 32 + mt * 16 + (lane >> 2);
            const int n  = bx * 128 + wn * 64 + j * 8 + (lane & 3) * 2;
            float2 lo2 = make_float2(acc[mt][j][0], acc[mt][j][1]);
            float2 hi2 = make_float2(acc[mt][j][2], acc[mt][j][3]);
            if (TRANS) {
                const int hh = n >> 6, dd = n & 63;
                const int bb0 = m0 >> 11, ss0 = m0 & (S - 1);
                const int m1 = m0 + 8;
                const int bb1 = m1 >> 11, ss1 = m1 & (S - 1);
                *reinterpret_cast<float2*>(
                    out + (((size_t)bb0 * H + hh) * S + ss0) * DH + dd) = lo2;
                *reinterpret_cast<float2*>(
                    out + (((size_t)bb1 * H + hh) * S + ss1) * DH + dd) = hi2;
            } else {
                *reinterpret_cast<float2*>(out + (size_t)m0 * E + n) = lo2;
                *reinterpret_cast<float2*>(out + (size_t)(m0 + 8) * E + n) = hi2;
            }
        }
}

// ---------------------------------------------------------------------------
// RoPE (in-place on [B*H, S, DH]); inv_freq from precomputed table.
// ---------------------------------------------------------------------------
__global__ void rope_kernel(float* __restrict__ x, float scale)
{
    constexpr int NP = B * H * S * (DH / 2);
    const int idx = blockIdx.x * blockDim.x + threadIdx.x;
    if (idx >= NP) return;
    const int i  = idx & 31;
    const int s  = (idx >> 5) & (S - 1);
    const int bh = idx >> 16;

    const float inv_freq = g_invfreq[i];
    const float ang = (float)s * inv_freq;
    float sn, cs;
    sincosf(ang, &sn, &cs);

    float2* p = reinterpret_cast<float2*>(x + (((size_t)bh * S + s) * DH) + 2 * i);
    float2 v = *p;
    const float xe = v.x, xo = v.y;
    v.x = (xe * cs - xo * sn) * scale;
    v.y = (xo * cs + xe * sn) * scale;
    *p = v;
}

// ---------------------------------------------------------------------------
// fp32 flash attention v2 (non-causal) — unchanged from round 2.
// ---------------------------------------------------------------------------
constexpr int FL_SQ   = 0;                 // [64][64]
constexpr int FL_SKP  = 64 * 64;           // K [128][64] swizzled / P [64][132]
constexpr int FL_SV   = FL_SKP + 64 * 132; // [128][64] even/odd split
constexpr int FL_SM   = FL_SV + 128 * 64;  // [64]
constexpr int FL_SL   = FL_SM + 64;        // [64]
constexpr int FL_SC   = FL_SL + 64;        // [64]
constexpr int FL_FLOATS = FL_SC + 64;
constexpr int FL_SMEM = FL_FLOATS * 4;     // 83712 B

__global__ void __launch_bounds__(256, 2)
flash_attn(const float* __restrict__ Q, const float* __restrict__ Kg,
           const float* __restrict__ Vg, float* __restrict__ AO)
{
    extern __shared__ float sm[];
    float* sQ  = sm + FL_SQ;
    float* sKP = sm + FL_SKP;
    float* sV  = sm + FL_SV;
    float* sM  = sm + FL_SM;
    float* sL  = sm + FL_SL;
    float* sC  = sm + FL_SC;

    const int tid = threadIdx.x;
    const int txk = tid & 15, tyk = tid >> 4;
    const int txv = tid & 7,  tyv = tid >> 3;
    const int q0 = blockIdx.x * 64;
    const int bh = blockIdx.z * H + blockIdx.y;
    const size_t qgbase = ((size_t)bh * S + q0) * DH;

#pragma unroll
    for (int rep = 0; rep < 4; rep++) {
        const int idx = rep * 256 + tid;
        const int r  = idx >> 4;
        const int c4 = (idx & 15) << 2;
        *reinterpret_cast<float4*>(&sQ[r * 64 + c4]) =
            *reinterpret_cast<const float4*>(Q + qgbase + r * 64 + c4);
    }
    if (tid < 64) { sM[tid] = -1e30f; sL[tid] = 0.f; }

    float o[2][8];
#pragma unroll
    for (int r = 0; r < 2; r++)
#pragma unroll
        for (int c = 0; c < 8; c++) o[r][c] = 0.f;

    for (int t = 0; t < S / 128; t++) {
        const size_t kgbase = ((size_t)bh * S + t * 128) * DH;
        __syncthreads();
#pragma unroll
        for (int rep = 0; rep < 8; rep++) {
            const int idx = rep * 256 + tid;
            const int r  = idx >> 4;
            const int c4 = (idx & 15) << 2;
            float4 kv = *reinterpret_cast<const float4*>(Kg + kgbase + r * 64 + c4);
            const int ksw = (((c4 >> 2) ^ (r >> 3)) & 15) << 2;
            *reinterpret_cast<float4*>(&sKP[r * 64 + ksw]) = kv;
            float4 vv = *reinterpret_cast<const float4*>(Vg + kgbase + r * 64 + c4);
            const int g = c4 >> 2;
            const int vp = ((g & 1) << 5) + ((g >> 1) << 2);
            *reinterpret_cast<float4*>(&sV[r * 64 + vp]) = vv;
        }
        __syncthreads();

        float acc[4][8];
#pragma unroll
        for (int i = 0; i < 4; i++)
#pragma unroll
            for (int j = 0; j < 8; j++) acc[i][j] = 0.f;

        const float* kbase = &sKP[(txk * 8) * 64];
#pragma unroll
        for (int kg = 0; kg < 16; kg++) {
            float4 qv[4];
#pragma unroll
            for (int i = 0; i < 4; i++)
                qv[i] = *reinterpret_cast<const float4*>(&sQ[(tyk * 4 + i) * 64 + kg * 4]);
            const int kcol = ((kg ^ txk) & 15) << 2;
#pragma unroll
            for (int jh = 0; jh < 2; jh++) {
                float4 kv[4];
#pragma unroll
                for (int jj = 0; jj < 4; jj++)
                    kv[jj] = *reinterpret_cast<const float4*>(&kbase[(jh * 4 + jj) * 64 + kcol]);
#pragma unroll
                for (int i = 0; i < 4; i++)
#pragma unroll
                    for (int jj = 0; jj < 4; jj++) {
                        const int j = jh * 4 + jj;
                        acc[i][j] += qv[i].x * kv[jj].x;
                        acc[i][j] += qv[i].y * kv[jj].y;
                        acc[i][j] += qv[i].z * kv[jj].z;
                        acc[i][j] += qv[i].w * kv[jj].w;
                    }
            }
        }

#pragma unroll
        for (int i = 0; i < 4; i++) {
            const int row = tyk * 4 + i;
            float mx = acc[i][0];
#pragma unroll
            for (int j = 1; j < 8; j++) mx = fmaxf(mx, acc[i][j]);
#pragma unroll
            for (int off = 8; off > 0; off >>= 1)
                mx = fmaxf(mx, __shfl_xor_sync(0xffffffffu, mx, off));
            const float oldm = sM[row];
            const float newm = fmaxf(oldm, mx);
            float ls = 0.f;
#pragma unroll
            for (int j = 0; j < 8; j++) {
                acc[i][j] = __expf(acc[i][j] - newm);
                ls += acc[i][j];
            }
#pragma unroll
            for (int off = 8; off > 0; off >>= 1)
                ls += __shfl_xor_sync(0xffffffffu, ls, off);
            if (txk == 0) {
                const float corr = __expf(oldm - newm);
                sM[row] = newm;
                sC[row] = corr;
                sL[row] = sL[row] * corr + ls;
            }
        }
        __syncthreads();

#pragma unroll
        for (int i = 0; i < 4; i++) {
            const int row = tyk * 4 + i;
            *reinterpret_cast<float4*>(&sKP[row * 132 + txk * 8]) =
                make_float4(acc[i][0], acc[i][1], acc[i][2], acc[i][3]);
            *reinterpret_cast<float4*>(&sKP[row * 132 + txk * 8 + 4]) =
                make_float4(acc[i][4], acc[i][5], acc[i][6], acc[i][7]);
        }
        __syncthreads();

        const int r0 = tyv * 2;
        const float c0 = sC[r0], c1 = sC[r0 + 1];
#pragma unroll
        for (int c = 0; c < 8; c++) { o[0][c] *= c0; o[1][c] *= c1; }

#pragma unroll 4
        for (int j4 = 0; j4 < 32; j4++) {
            float4 p0 = *reinterpret_cast<const float4*>(&sKP[r0 * 132 + j4 * 4]);
            float4 p1 = *reinterpret_cast<const float4*>(&sKP[(r0 + 1) * 132 + j4 * 4]);
            float pr0[4] = {p0.x, p0.y, p0.z, p0.w};
            float pr1[4] = {p1.x, p1.y, p1.z, p1.w};
#pragma unroll
            for (int jj = 0; jj < 4; jj++) {
                const int j = j4 * 4 + jj;
                float4 v0 = *reinterpret_cast<const float4*>(&sV[j * 64 + txv * 4]);
                float4 v1 = *reinterpret_cast<const float4*>(&sV[j * 64 + 32 + txv * 4]);
                o[0][0] += pr0[jj] * v0.x; o[0][1] += pr0[jj] * v0.y;
                o[0][2] += pr0[jj] * v0.z; o[0][3] += pr0[jj] * v0.w;
                o[0][4] += pr0[jj] * v1.x; o[0][5] += pr0[jj] * v1.y;
                o[0][6] += pr0[jj] * v1.z; o[0][7] += pr0[jj] * v1.w;
                o[1][0] += pr1[jj] * v0.x; o[1][1] += pr1[jj] * v0.y;
                o[1][2] += pr1[jj] * v0.z; o[1][3] += pr1[jj] * v0.w;
                o[1][4] += pr1[jj] * v1.x; o[1][5] += pr1[jj] * v1.y;
                o[1][6] += pr1[jj] * v1.z; o[1][7] += pr1[jj] * v1.w;
            }
        }
    }

    const int r0 = tyv * 2;
    const float inv0 = 1.f / sL[r0];
    const float inv1 = 1.f / sL[r0 + 1];
    float* d0 = &AO[((size_t)blockIdx.z * S + q0 + r0) * E + blockIdx.y * 64 + txv * 8];
    float* d1 = d0 + E;
    *reinterpret_cast<float4*>(d0) =
        make_float4(o[0][0] * inv0, o[0][1] * inv0, o[0][2] * inv0, o[0][3] * inv0);
    *reinterpret_cast<float4*>(d0 + 4) =
        make_float4(o[0][4] * inv0, o[0][5] * inv0, o[0][6] * inv0, o[0][7] * inv0);
    *reinterpret_cast<float4*>(d1) =
        make_float4(o[1][0] * inv1, o[1][1] * inv1, o[1][2] * inv1, o[1][3] * inv1);
    *reinterpret_cast<float4*>(d1 + 4) =
        make_float4(o[1][4] * inv1, o[1][5] * inv1, o[1][6] * inv1, o[1][7] * inv1);
}

// ---------------------------------------------------------------------------
extern "C" void kernel_launch(void* const* d_in, const int* in_sizes, int n_in,
                              void* d_out, int out_size)
{
    const float* q  = (const float*)d_in[0];
    const float* k  = (const float*)d_in[1];
    const float* v  = (const float*)d_in[2];
    const float* Wq = (const float*)d_in[3];
    const float* Wk = (const float*)d_in[4];
    const float* Wv = (const float*)d_in[5];
    const float* Wo = (const float*)d_in[6];
    float* out = (float*)d_out;

    float *pQ, *pK, *pV, *pAO;
    __nv_bfloat16 *aH, *aL, *wH, *wL;
    cudaGetSymbolAddress((void**)&pQ,  g_Q);
    cudaGetSymbolAddress((void**)&pK,  g_K);
    cudaGetSymbolAddress((void**)&pV,  g_V);
    cudaGetSymbolAddress((void**)&pAO, g_AO);
    cudaGetSymbolAddress((void**)&aH,  g_aH);
    cudaGetSymbolAddress((void**)&aL,  g_aL);
    cudaGetSymbolAddress((void**)&wH,  g_wH);
    cudaGetSymbolAddress((void**)&wL,  g_wL);

    cudaFuncSetAttribute(flash_attn,
                         cudaFuncAttributeMaxDynamicSharedMemorySize, FL_SMEM);

    init_invfreq_kernel<<<1, 32>>>();

    constexpr int NA4 = M_TOT * E / 4;   // activation float4 count
    constexpr int NW4 = E * E / 4;       // weight float4 count
    dim3 gg(E / 128, M_TOT / 128);       // (8, 32)

    convert_split<<<NW4 / 256, 256>>>(Wq, wH, wL, NW4);
    convert_split<<<NA4 / 256, 256>>>(q, aH, aL, NA4);
    gemm_mma<true><<<gg, 256>>>(aH, aL, wH, wL, pQ);

    convert_split<<<NW4 / 256, 256>>>(Wk, wH, wL, NW4);
    convert_split<<<NA4 / 256, 256>>>(k, aH, aL, NA4);
    gemm_mma<true><<<gg, 256>>>(aH, aL, wH, wL, pK);

    convert_split<<<NW4 / 256, 256>>>(Wv, wH, wL, NW4);
    convert_split<<<NA4 / 256, 256>>>(v, aH, aL, NA4);
    gemm_mma<true><<<gg, 256>>>(aH, aL, wH, wL, pV);

    constexpr int NP = B * H * S * (DH / 2);
    rope_kernel<<<(NP + 255) / 256, 256>>>(pQ, 0.03125f);  // fold 1/sqrt(E)
    rope_kernel<<<(NP + 255) / 256, 256>>>(pK, 1.0f);

    dim3 ag(S / 64, H, B);
    flash_attn<<<ag, 256, FL_SMEM>>>(pQ, pK, pV, pAO);

    convert_split<<<NW4 / 256, 256>>>(Wo, wH, wL, NW4);
    convert_split<<<NA4 / 256, 256>>>(pAO, aH, aL, NA4);
    gemm_mma<false><<<gg, 256>>>(aH, aL, wH, wL, out);
}

// round 4
// speedup vs baseline: 3.2205x; 1.8582x over previous
#include <cuda_runtime.h>
#include <cuda_bf16.h>
#include <math.h>
#include <stdint.h>

// Problem constants
constexpr int B  = 2;
constexpr int S  = 2048;
constexpr int E  = 1024;
constexpr int H  = 16;
constexpr int DH = 64;
constexpr int M_TOT = B * S;          // 4096

// Scratch (allocation-free rule: __device__ globals)
__device__ float g_Q[(size_t)B * H * S * DH];
__device__ float g_K[(size_t)B * H * S * DH];
__device__ float g_V[(size_t)B * H * S * DH];
__device__ float g_invfreq[32];
// bf16 hi/lo split buffers
__device__ __nv_bfloat16 g_aH[(size_t)M_TOT * E];
__device__ __nv_bfloat16 g_aL[(size_t)M_TOT * E];
__device__ __nv_bfloat16 g_wH[(size_t)E * E];
__device__ __nv_bfloat16 g_wL[(size_t)E * E];
__device__ __nv_bfloat16 g_Qh[(size_t)B * H * S * DH];
__device__ __nv_bfloat16 g_Ql[(size_t)B * H * S * DH];
__device__ __nv_bfloat16 g_Kh[(size_t)B * H * S * DH];
__device__ __nv_bfloat16 g_Kl[(size_t)B * H * S * DH];
__device__ __nv_bfloat16 g_Vth[(size_t)B * H * DH * S];  // [bh][dh][s]
__device__ __nv_bfloat16 g_Vtl[(size_t)B * H * DH * S];

// ---------------------------------------------------------------------------
__global__ void init_invfreq_kernel()
{
    const int i = threadIdx.x;
    g_invfreq[i] = (float)pow(10000.0, -(double)(2 * i) / 64.0);
}

// ---------------------------------------------------------------------------
// fp32 -> bf16 hi/lo split
// ---------------------------------------------------------------------------
__global__ void __launch_bounds__(256)
convert_split(const float* __restrict__ x, __nv_bfloat16* __restrict__ hi,
              __nv_bfloat16* __restrict__ lo, int n4)
{
    const int i = blockIdx.x * blockDim.x + threadIdx.x;
    if (i >= n4) return;
    float4 v = reinterpret_cast<const float4*>(x)[i];
    __nv_bfloat16 h0 = __float2bfloat16(v.x);
    __nv_bfloat16 h1 = __float2bfloat16(v.y);
    __nv_bfloat16 h2 = __float2bfloat16(v.z);
    __nv_bfloat16 h3 = __float2bfloat16(v.w);
    __nv_bfloat16 l0 = __float2bfloat16(v.x - __bfloat162float(h0));
    __nv_bfloat16 l1 = __float2bfloat16(v.y - __bfloat162float(h1));
    __nv_bfloat16 l2 = __float2bfloat16(v.z - __bfloat162float(h2));
    __nv_bfloat16 l3 = __float2bfloat16(v.w - __bfloat162float(h3));
    __nv_bfloat162 hp0{h0, h1}, hp1{h2, h3}, lp0{l0, l1}, lp1{l2, l3};
    uint2 hu, lu;
    hu.x = *reinterpret_cast<uint32_t*>(&hp0);
    hu.y = *reinterpret_cast<uint32_t*>(&hp1);
    lu.x = *reinterpret_cast<uint32_t*>(&lp0);
    lu.y = *reinterpret_cast<uint32_t*>(&lp1);
    *reinterpret_cast<uint2*>(hi + 4 * (size_t)i) = hu;
    *reinterpret_cast<uint2*>(lo + 4 * (size_t)i) = lu;
}

// ---------------------------------------------------------------------------
// MMA helpers
// ---------------------------------------------------------------------------
__device__ __forceinline__ uint32_t smem_u32(const void* p)
{
    uint32_t a;
    asm("{ .reg .u64 t; cvta.to.shared.u64 t, %1; cvt.u32.u64 %0, t; }"
        : "=r"(a) : "l"(p));
    return a;
}
__device__ __forceinline__ void ldsm4(uint32_t* r, uint32_t addr)
{
    asm volatile("ldmatrix.sync.aligned.m8n8.x4.shared.b16 {%0,%1,%2,%3}, [%4];"
                 : "=r"(r[0]), "=r"(r[1]), "=r"(r[2]), "=r"(r[3]) : "r"(addr));
}
__device__ __forceinline__ void mma16816(float* c, const uint32_t* a,
                                         const uint32_t* b)
{
    asm volatile("mma.sync.aligned.m16n8k16.row.col.f32.bf16.bf16.f32 "
                 "{%0,%1,%2,%3}, {%4,%5,%6,%7}, {%8,%9}, {%0,%1,%2,%3};"
                 : "+f"(c[0]), "+f"(c[1]), "+f"(c[2]), "+f"(c[3])
                 : "r"(a[0]), "r"(a[1]), "r"(a[2]), "r"(a[3]),
                   "r"(b[0]), "r"(b[1]));
}
__device__ __forceinline__ void split2(float x, float y, uint32_t& h, uint32_t& l)
{
    __nv_bfloat16 hx = __float2bfloat16(x), hy = __float2bfloat16(y);
    __nv_bfloat16 lx = __float2bfloat16(x - __bfloat162float(hx));
    __nv_bfloat16 ly = __float2bfloat16(y - __bfloat162float(hy));
    __nv_bfloat162 hp{hx, hy}, lp{lx, ly};
    h = *reinterpret_cast<uint32_t*>(&hp);
    l = *reinterpret_cast<uint32_t*>(&lp);
}
// swizzled byte offset, [rows][32 bf16] (64B rows)
__device__ __forceinline__ uint32_t swz64(int row, int c)
{
    return (uint32_t)(row * 64 + ((c ^ ((row >> 1) & 3)) << 4));
}
// swizzled byte offset, [rows][64 bf16] (128B rows, 8 chunks)
__device__ __forceinline__ uint32_t swz128(int row, int c)
{
    return (uint32_t)(row * 128 + ((c ^ (row & 7)) << 4));
}
// swizzled byte offset, [rows][128 bf16] (256B rows, 16 chunks)
__device__ __forceinline__ uint32_t swz256(int row, int c)
{
    return (uint32_t)(row * 256 + ((c ^ (row & 7)) << 4));
}

// ---------------------------------------------------------------------------
// Tensor-core GEMM (bf16 hi/lo split): out = A @ B^T  (round-3, unchanged)
// ---------------------------------------------------------------------------
template <bool TRANS>
__global__ void __launch_bounds__(256)
gemm_mma(const __nv_bfloat16* __restrict__ Ahg, const __nv_bfloat16* __restrict__ Alg,
         const __nv_bfloat16* __restrict__ Bhg, const __nv_bfloat16* __restrict__ Blg,
         float* __restrict__ out)
{
    __shared__ __align__(16) uint8_t smem[32768];
    constexpr uint32_t oAh = 0, oAl = 8192, oBh = 16384, oBl = 24576;
    const uint32_t sbase = smem_u32(smem);

    const int tid  = threadIdx.x;
    const int warp = tid >> 5, lane = tid & 31;
    const int wm = warp & 3;
    const int wn = warp >> 2;
    const int bx = blockIdx.x, by = blockIdx.y;

    const int lr = tid >> 1, lhalf = tid & 1;
    const size_t aoff = (size_t)(by * 128 + lr) * E + lhalf * 16;
    const size_t boff = (size_t)(bx * 128 + lr) * E + lhalf * 16;
    const uint32_t w0 = swz64(lr, lhalf * 2);
    const uint32_t w1 = swz64(lr, lhalf * 2 + 1);

    uint32_t adA[2][2], adB[4][2];
#pragma unroll
    for (int s = 0; s < 2; s++) {
#pragma unroll
        for (int mt = 0; mt < 2; mt++)
            adA[mt][s] = swz64(wm * 32 + mt * 16 + (lane & 15), s * 2 + (lane >> 4));
#pragma unroll
        for (int g = 0; g < 4; g++)
            adB[g][s] = swz64(wn * 64 + g * 16 + ((lane >> 1) & 8) + (lane & 7),
                              s * 2 + ((lane >> 3) & 1));
    }

    float acc[2][8][4];
#pragma unroll
    for (int mt = 0; mt < 2; mt++)
#pragma unroll
        for (int j = 0; j < 8; j++)
#pragma unroll
            for (int r = 0; r < 4; r++) acc[mt][j][r] = 0.f;

#pragma unroll 1
    for (int k0 = 0; k0 < E; k0 += 32) {
        uint4 vAh0 = *reinterpret_cast<const uint4*>(Ahg + aoff + k0);
        uint4 vAh1 = *reinterpret_cast<const uint4*>(Ahg + aoff + k0 + 8);
        uint4 vAl0 = *reinterpret_cast<const uint4*>(Alg + aoff + k0);
        uint4 vAl1 = *reinterpret_cast<const uint4*>(Alg + aoff + k0 + 8);
        uint4 vBh0 = *reinterpret_cast<const uint4*>(Bhg + boff + k0);
        uint4 vBh1 = *reinterpret_cast<const uint4*>(Bhg + boff + k0 + 8);
        uint4 vBl0 = *reinterpret_cast<const uint4*>(Blg + boff + k0);
        uint4 vBl1 = *reinterpret_cast<const uint4*>(Blg + boff + k0 + 8);
        __syncthreads();
        *reinterpret_cast<uint4*>(smem + oAh + w0) = vAh0;
        *reinterpret_cast<uint4*>(smem + oAh + w1) = vAh1;
        *reinterpret_cast<uint4*>(smem + oAl + w0) = vAl0;
        *reinterpret_cast<uint4*>(smem + oAl + w1) = vAl1;
        *reinterpret_cast<uint4*>(smem + oBh + w0) = vBh0;
        *reinterpret_cast<uint4*>(smem + oBh + w1) = vBh1;
        *reinterpret_cast<uint4*>(smem + oBl + w0) = vBl0;
        *reinterpret_cast<uint4*>(smem + oBl + w1) = vBl1;
        __syncthreads();

#pragma unroll
        for (int s = 0; s < 2; s++) {
            uint32_t fAh[2][4], fAl[2][4], fBh[4][4], fBl[4][4];
#pragma unroll
            for (int mt = 0; mt < 2; mt++) {
                ldsm4(fAh[mt], sbase + oAh + adA[mt][s]);
                ldsm4(fAl[mt], sbase + oAl + adA[mt][s]);
            }
#pragma unroll
            for (int g = 0; g < 4; g++) {
                ldsm4(fBh[g], sbase + oBh + adB[g][s]);
                ldsm4(fBl[g], sbase + oBl + adB[g][s]);
            }
#pragma unroll
            for (int mt = 0; mt < 2; mt++)
#pragma unroll
                for (int j = 0; j < 8; j++) {
                    const int g = j >> 1, p = (j & 1) * 2;
                    uint32_t bh[2] = {fBh[g][p], fBh[g][p + 1]};
                    uint32_t bl[2] = {fBl[g][p], fBl[g][p + 1]};
                    mma16816(acc[mt][j], fAh[mt], bh);
                    mma16816(acc[mt][j], fAh[mt], bl);
                    mma16816(acc[mt][j], fAl[mt], bh);
                }
        }
    }

#pragma unroll
    for (int mt = 0; mt < 2; mt++)
#pragma unroll
        for (int j = 0; j < 8; j++) {
            const int m0 = by * 128 + wm * 32 + mt * 16 + (lane >> 2);
            const int n  = bx * 128 + wn * 64 + j * 8 + (lane & 3) * 2;
            float2 lo2 = make_float2(acc[mt][j][0], acc[mt][j][1]);
            float2 hi2 = make_float2(acc[mt][j][2], acc[mt][j][3]);
            if (TRANS) {
                const int hh = n >> 6, dd = n & 63;
                const int bb0 = m0 >> 11, ss0 = m0 & (S - 1);
                const int m1 = m0 + 8;
                const int bb1 = m1 >> 11, ss1 = m1 & (S - 1);
                *reinterpret_cast<float2*>(
                    out + (((size_t)bb0 * H + hh) * S + ss0) * DH + dd) = lo2;
                *reinterpret_cast<float2*>(
                    out + (((size_t)bb1 * H + hh) * S + ss1) * DH + dd) = hi2;
            } else {
                *reinterpret_cast<float2*>(out + (size_t)m0 * E + n) = lo2;
                *reinterpret_cast<float2*>(out + (size_t)(m0 + 8) * E + n) = hi2;
            }
        }
}

// ---------------------------------------------------------------------------
// RoPE + bf16 hi/lo split: fp32 in, split bf16 out (same [bh][s][64] layout)
// ---------------------------------------------------------------------------
__global__ void rope_split(const float* __restrict__ x,
                           __nv_bfloat16* __restrict__ hi,
                           __nv_bfloat16* __restrict__ lo, float scale)
{
    constexpr int NP = B * H * S * (DH / 2);
    const int idx = blockIdx.x * blockDim.x + threadIdx.x;
    if (idx >= NP) return;
    const int i  = idx & 31;
    const int s  = (idx >> 5) & (S - 1);
    const int bh = idx >> 16;

    const float ang = (float)s * g_invfreq[i];
    float sn, cs;
    sincosf(ang, &sn, &cs);

    const size_t off = (((size_t)bh * S + s) * DH) + 2 * i;
    float2 v = *reinterpret_cast<const float2*>(x + off);
    const float rx = (v.x * cs - v.y * sn) * scale;
    const float ry = (v.y * cs + v.x * sn) * scale;
    uint32_t h, l;
    split2(rx, ry, h, l);
    *reinterpret_cast<uint32_t*>(hi + off) = h;
    *reinterpret_cast<uint32_t*>(lo + off) = l;
}

// ---------------------------------------------------------------------------
// V transpose + split: [bh][s][64] fp32 -> [bh][64][s] bf16 hi/lo
// grid (S/64, B*H), 256 threads, 64x64 smem tile
// ---------------------------------------------------------------------------
__global__ void __launch_bounds__(256)
vtrans_split(const float* __restrict__ Vf, __nv_bfloat16* __restrict__ hi,
             __nv_bfloat16* __restrict__ lo)
{
    __shared__ float tile[64][65];
    const int tid = threadIdx.x;
    const int s0 = blockIdx.x * 64;
    const int bh = blockIdx.y;

#pragma unroll
    for (int rep = 0; rep < 4; rep++) {
        const int idx = rep * 256 + tid;
        const int r  = idx >> 4;           // s row
        const int c4 = (idx & 15) << 2;    // dh
        float4 v = *reinterpret_cast<const float4*>(
            Vf + ((size_t)bh * S + s0 + r) * DH + c4);
        tile[c4 + 0][r] = v.x;
        tile[c4 + 1][r] = v.y;
        tile[c4 + 2][r] = v.z;
        tile[c4 + 3][r] = v.w;
    }
    __syncthreads();
#pragma unroll
    for (int rep = 0; rep < 4; rep++) {
        const int idx = rep * 256 + tid;
        const int dh = idx >> 4;
        const int s4 = (idx & 15) << 2;
        uint32_t h0, l0, h1, l1;
        split2(tile[dh][s4], tile[dh][s4 + 1], h0, l0);
        split2(tile[dh][s4 + 2], tile[dh][s4 + 3], h1, l1);
        const size_t off = ((size_t)bh * DH + dh) * S + s0 + s4;
        *reinterpret_cast<uint2*>(hi + off) = make_uint2(h0, h1);
        *reinterpret_cast<uint2*>(lo + off) = make_uint2(l0, l1);
    }
}

// ---------------------------------------------------------------------------
// MMA flash attention (non-causal), bf16 hi/lo split on both GEMMs.
// Grid (S/128, H, B), 256 threads (8 warps); warp w owns q rows [16w,16w+16).
// smem: Qh/Ql/Kh/Kl [128][64], Vth/Vtl [64][128] (all swizzled) = 96 KB.
// Epilogue writes split bf16 activations (aH/aL) for the output projection.
// ---------------------------------------------------------------------------
constexpr int FA_oQh = 0;
constexpr int FA_oQl = 16384;
constexpr int FA_oKh = 32768;
constexpr int FA_oKl = 49152;
constexpr int FA_oVh = 65536;
constexpr int FA_oVl = 81920;
constexpr int FA_SMEM = 98304;

__global__ void __launch_bounds__(256)
flash_mma(const __nv_bfloat16* __restrict__ Qh, const __nv_bfloat16* __restrict__ Ql,
          const __nv_bfloat16* __restrict__ Kh, const __nv_bfloat16* __restrict__ Kl,
          const __nv_bfloat16* __restrict__ Vth, const __nv_bfloat16* __restrict__ Vtl,
          __nv_bfloat16* __restrict__ aH, __nv_bfloat16* __restrict__ aL)
{
    extern __shared__ __align__(16) uint8_t sm8[];
    const uint32_t sbase = smem_u32(sm8);

    const int tid = threadIdx.x;
    const int warp = tid >> 5, lane = tid & 31;
    const int q0 = blockIdx.x * 128;
    const int hh = blockIdx.y, bb = blockIdx.z;
    const int bh = bb * H + hh;

    // load Q tile hi/lo ([128][64] bf16, swizzled 128B rows)
#pragma unroll
    for (int rep = 0; rep < 4; rep++) {
        const int idx = rep * 256 + tid;
        const int r = idx >> 3, c = idx & 7;
        const size_t go = ((size_t)bh * S + q0 + r) * DH + c * 8;
        const uint32_t so = swz128(r, c);
        *reinterpret_cast<uint4*>(sm8 + FA_oQh + so) =
            *reinterpret_cast<const uint4*>(Qh + go);
        *reinterpret_cast<uint4*>(sm8 + FA_oQl + so) =
            *reinterpret_cast<const uint4*>(Ql + go);
    }

    float m_run[2] = {-1e30f, -1e30f};
    float l_run[2] = {0.f, 0.f};
    float o[8][4];
#pragma unroll
    for (int j = 0; j < 8; j++)
#pragma unroll
        for (int r = 0; r < 4; r++) o[j][r] = 0.f;

    // ldmatrix address components
    const int aQrow = warp * 16 + (lane & 15);
    const int aQcs  = lane >> 4;
    const int bRow8 = ((lane >> 1) & 8) + (lane & 7);
    const int bCs   = (lane >> 3) & 1;

#pragma unroll 1
    for (int t = 0; t < S / 128; t++) {
        __syncthreads();
        // load K [128][64] and Vt [64][128] tiles (hi/lo)
#pragma unroll
        for (int rep = 0; rep < 4; rep++) {
            const int idx = rep * 256 + tid;
            {
                const int r = idx >> 3, c = idx & 7;
                const size_t go = ((size_t)bh * S + t * 128 + r) * DH + c * 8;
                const uint32_t so = swz128(r, c);
                *reinterpret_cast<uint4*>(sm8 + FA_oKh + so) =
                    *reinterpret_cast<const uint4*>(Kh + go);
                *reinterpret_cast<uint4*>(sm8 + FA_oKl + so) =
                    *reinterpret_cast<const uint4*>(Kl + go);
            }
            {
                const int r = idx >> 4, c = idx & 15;
                const size_t go = ((size_t)bh * DH + r) * S + t * 128 + c * 8;
                const uint32_t so = swz256(r, c);
                *reinterpret_cast<uint4*>(sm8 + FA_oVh + so) =
                    *reinterpret_cast<const uint4*>(Vth + go);
                *reinterpret_cast<uint4*>(sm8 + FA_oVl + so) =
                    *reinterpret_cast<const uint4*>(Vtl + go);
            }
        }
        __syncthreads();

        // ---- S = Q K^T : acc[16 n8-frags][4] ----
        float acc[16][4];
#pragma unroll
        for (int j = 0; j < 16; j++)
#pragma unroll
            for (int r = 0; r < 4; r++) acc[j][r] = 0.f;

#pragma unroll
        for (int s = 0; s < 4; s++) {
            uint32_t ah[4], al[4];
            const uint32_t qoff = swz128(aQrow, 2 * s + aQcs);
            ldsm4(ah, sbase + FA_oQh + qoff);
            ldsm4(al, sbase + FA_oQl + qoff);
#pragma unroll
            for (int g = 0; g < 8; g++) {
                const uint32_t koff = swz128(g * 16 + bRow8, 2 * s + bCs);
                uint32_t kbh[4], kbl[4];
                ldsm4(kbh, sbase + FA_oKh + koff);
                ldsm4(kbl, sbase + FA_oKl + koff);
#pragma unroll
                for (int jj = 0; jj < 2; jj++) {
                    const int j = g * 2 + jj, p = jj * 2;
                    uint32_t bH[2] = {kbh[p], kbh[p + 1]};
                    uint32_t bL[2] = {kbl[p], kbl[p + 1]};
                    mma16816(acc[j], ah, bH);
                    mma16816(acc[j], ah, bL);
                    mma16816(acc[j], al, bH);
                }
            }
        }

        // ---- online softmax (rows lane>>2 and lane>>2+8; quad shuffles) ----
#pragma unroll
        for (int rh = 0; rh < 2; rh++) {
            const int c0 = rh * 2, c1 = rh * 2 + 1;
            float mx = acc[0][c0];
#pragma unroll
            for (int j = 0; j < 16; j++)
                mx = fmaxf(mx, fmaxf(acc[j][c0], acc[j][c1]));
            mx = fmaxf(mx, __shfl_xor_sync(0xffffffffu, mx, 1));
            mx = fmaxf(mx, __shfl_xor_sync(0xffffffffu, mx, 2));
            const float newm = fmaxf(m_run[rh], mx);
            const float corr = __expf(m_run[rh] - newm);
            m_run[rh] = newm;
            float ls = 0.f;
#pragma unroll
            for (int j = 0; j < 16; j++) {
                acc[j][c0] = __expf(acc[j][c0] - newm);
                acc[j][c1] = __expf(acc[j][c1] - newm);
                ls += acc[j][c0] + acc[j][c1];
            }
            ls += __shfl_xor_sync(0xffffffffu, ls, 1);
            ls += __shfl_xor_sync(0xffffffffu, ls, 2);
            l_run[rh] = l_run[rh] * corr + ls;
#pragma unroll
            for (int j = 0; j < 8; j++) {
                o[j][c0] *= corr;
                o[j][c1] *= corr;
            }
        }

        // ---- O += P V : P split in registers, V from swizzled smem ----
#pragma unroll
        for (int s = 0; s < 8; s++) {
            uint32_t pah[4], pal[4];
            split2(acc[2 * s][0], acc[2 * s][1], pah[0], pal[0]);
            split2(acc[2 * s][2], acc[2 * s][3], pah[1], pal[1]);
            split2(acc[2 * s + 1][0], acc[2 * s + 1][1], pah[2], pal[2]);
            split2(acc[2 * s + 1][2], acc[2 * s + 1][3], pah[3], pal[3]);
#pragma unroll
            for (int ng = 0; ng < 4; ng++) {
                const uint32_t voff = swz256(ng * 16 + bRow8, 2 * s + bCs);
                uint32_t vbh[4], vbl[4];
                ldsm4(vbh, sbase + FA_oVh + voff);
                ldsm4(vbl, sbase + FA_oVl + voff);
#pragma unroll
                for (int jj = 0; jj < 2; jj++) {
                    const int j = ng * 2 + jj, p = jj * 2;
                    uint32_t bH[2] = {vbh[p], vbh[p + 1]};
                    uint32_t bL[2] = {vbl[p], vbl[p + 1]};
                    mma16816(o[j], pah, bH);
                    mma16816(o[j], pah, bL);
                    mma16816(o[j], pal, bH);
                }
            }
        }
    }

    // epilogue: normalize, split to bf16 hi/lo, write [B,S,E] activations
    const float inv0 = 1.f / l_run[0];
    const float inv1 = 1.f / l_run[1];
    const int r0 = q0 + warp * 16 + (lane >> 2);
    const int r1 = r0 + 8;
#pragma unroll
    for (int j = 0; j < 8; j++) {
        const int col = hh * 64 + j * 8 + (lane & 3) * 2;
        const size_t off0 = ((size_t)bb * S + r0) * E + col;
        const size_t off1 = ((size_t)bb * S + r1) * E + col;
        uint32_t h, l;
        split2(o[j][0] * inv0, o[j][1] * inv0, h, l);
        *reinterpret_cast<uint32_t*>(aH + off0) = h;
        *reinterpret_cast<uint32_t*>(aL + off0) = l;
        split2(o[j][2] * inv1, o[j][3] * inv1, h, l);
        *reinterpret_cast<uint32_t*>(aH + off1) = h;
        *reinterpret_cast<uint32_t*>(aL + off1) = l;
    }
}

// ---------------------------------------------------------------------------
extern "C" void kernel_launch(void* const* d_in, const int* in_sizes, int n_in,
                              void* d_out, int out_size)
{
    const float* q  = (const float*)d_in[0];
    const float* k  = (const float*)d_in[1];
    const float* v  = (const float*)d_in[2];
    const float* Wq = (const float*)d_in[3];
    const float* Wk = (const float*)d_in[4];
    const float* Wv = (const float*)d_in[5];
    const float* Wo = (const float*)d_in[6];
    float* out = (float*)d_out;

    float *pQ, *pK, *pV;
    __nv_bfloat16 *aH, *aL, *wH, *wL, *qh, *ql, *kh, *kl, *vth, *vtl;
    cudaGetSymbolAddress((void**)&pQ,  g_Q);
    cudaGetSymbolAddress((void**)&pK,  g_K);
    cudaGetSymbolAddress((void**)&pV,  g_V);
    cudaGetSymbolAddress((void**)&aH,  g_aH);
    cudaGetSymbolAddress((void**)&aL,  g_aL);
    cudaGetSymbolAddress((void**)&wH,  g_wH);
    cudaGetSymbolAddress((void**)&wL,  g_wL);
    cudaGetSymbolAddress((void**)&qh,  g_Qh);
    cudaGetSymbolAddress((void**)&ql,  g_Ql);
    cudaGetSymbolAddress((void**)&kh,  g_Kh);
    cudaGetSymbolAddress((void**)&kl,  g_Kl);
    cudaGetSymbolAddress((void**)&vth, g_Vth);
    cudaGetSymbolAddress((void**)&vtl, g_Vtl);

    cudaFuncSetAttribute(flash_mma,
                         cudaFuncAttributeMaxDynamicSharedMemorySize, FA_SMEM);

    init_invfreq_kernel<<<1, 32>>>();

    constexpr int NA4 = M_TOT * E / 4;
    constexpr int NW4 = E * E / 4;
    dim3 gg(E / 128, M_TOT / 128);

    convert_split<<<NW4 / 256, 256>>>(Wq, wH, wL, NW4);
    convert_split<<<NA4 / 256, 256>>>(q, aH, aL, NA4);
    gemm_mma<true><<<gg, 256>>>(aH, aL, wH, wL, pQ);

    convert_split<<<NW4 / 256, 256>>>(Wk, wH, wL, NW4);
    convert_split<<<NA4 / 256, 256>>>(k, aH, aL, NA4);
    gemm_mma<true><<<gg, 256>>>(aH, aL, wH, wL, pK);

    convert_split<<<NW4 / 256, 256>>>(Wv, wH, wL, NW4);
    convert_split<<<NA4 / 256, 256>>>(v, aH, aL, NA4);
    gemm_mma<true><<<gg, 256>>>(aH, aL, wH, wL, pV);

    constexpr int NP = B * H * S * (DH / 2);
    rope_split<<<(NP + 255) / 256, 256>>>(pQ, qh, ql, 0.03125f);  // fold 1/sqrt(E)
    rope_split<<<(NP + 255) / 256, 256>>>(pK, kh, kl, 1.0f);
    vtrans_split<<<dim3(S / 64, B * H), 256>>>(pV, vth, vtl);

    dim3 ag(S / 128, H, B);
    flash_mma<<<ag, 256, FA_SMEM>>>(qh, ql, kh, kl, vth, vtl, aH, aL);

    convert_split<<<NW4 / 256, 256>>>(Wo, wH, wL, NW4);
    gemm_mma<false><<<gg, 256>>>(aH, aL, wH, wL, out);
}

// round 5
// speedup vs baseline: 3.2547x; 1.0106x over previous
#include <cuda_runtime.h>
#include <cuda_bf16.h>
#include <math.h>
#include <stdint.h>

// Problem constants
constexpr int B  = 2;
constexpr int S  = 2048;
constexpr int E  = 1024;
constexpr int H  = 16;
constexpr int DH = 64;
constexpr int M_TOT = B * S;          // 4096

// Scratch (allocation-free rule: __device__ globals)
__device__ float g_V[(size_t)B * H * S * DH];
__device__ float g_AO[(size_t)B * S * E];
__device__ float g_invfreq[32];
__device__ __nv_bfloat16 g_Qh[(size_t)B * H * S * DH];
__device__ __nv_bfloat16 g_Ql[(size_t)B * H * S * DH];
__device__ __nv_bfloat16 g_Kh[(size_t)B * H * S * DH];
__device__ __nv_bfloat16 g_Kl[(size_t)B * H * S * DH];
__device__ __nv_bfloat16 g_Vth[(size_t)B * H * DH * S];  // [bh][dh][s]
__device__ __nv_bfloat16 g_Vtl[(size_t)B * H * DH * S];

// ---------------------------------------------------------------------------
__global__ void init_invfreq_kernel()
{
    const int i = threadIdx.x;
    g_invfreq[i] = (float)pow(10000.0, -(double)(2 * i) / 64.0);
}

// ---------------------------------------------------------------------------
// helpers
// ---------------------------------------------------------------------------
__device__ __forceinline__ uint32_t smem_u32(const void* p)
{
    uint32_t a;
    asm("{ .reg .u64 t; cvta.to.shared.u64 t, %1; cvt.u32.u64 %0, t; }"
        : "=r"(a) : "l"(p));
    return a;
}
__device__ __forceinline__ void ldsm4(uint32_t* r, uint32_t addr)
{
    asm volatile("ldmatrix.sync.aligned.m8n8.x4.shared.b16 {%0,%1,%2,%3}, [%4];"
                 : "=r"(r[0]), "=r"(r[1]), "=r"(r[2]), "=r"(r[3]) : "r"(addr));
}
__device__ __forceinline__ void mma16816(float* c, const uint32_t* a,
                                         const uint32_t* b)
{
    asm volatile("mma.sync.aligned.m16n8k16.row.col.f32.bf16.bf16.f32 "
                 "{%0,%1,%2,%3}, {%4,%5,%6,%7}, {%8,%9}, {%0,%1,%2,%3};"
                 : "+f"(c[0]), "+f"(c[1]), "+f"(c[2]), "+f"(c[3])
                 : "r"(a[0]), "r"(a[1]), "r"(a[2]), "r"(a[3]),
                   "r"(b[0]), "r"(b[1]));
}
__device__ __forceinline__ void split2(float x, float y, uint32_t& h, uint32_t& l)
{
    __nv_bfloat16 hx = __float2bfloat16(x), hy = __float2bfloat16(y);
    __nv_bfloat16 lx = __float2bfloat16(x - __bfloat162float(hx));
    __nv_bfloat16 ly = __float2bfloat16(y - __bfloat162float(hy));
    __nv_bfloat162 hp{hx, hy}, lp{lx, ly};
    h = *reinterpret_cast<uint32_t*>(&hp);
    l = *reinterpret_cast<uint32_t*>(&lp);
}
__device__ __forceinline__ void split8(const float4& a, const float4& b,
                                       uint4& h, uint4& l)
{
    split2(a.x, a.y, h.x, l.x);
    split2(a.z, a.w, h.y, l.y);
    split2(b.x, b.y, h.z, l.z);
    split2(b.z, b.w, h.w, l.w);
}
// swizzled byte offset, [rows][32 bf16] (64B rows)
__device__ __forceinline__ uint32_t swz64(int row, int c)
{
    return (uint32_t)(row * 64 + ((c ^ ((row >> 1) & 3)) << 4));
}
// swizzled byte offset, [rows][64 bf16] (128B rows)
__device__ __forceinline__ uint32_t swz128(int row, int c)
{
    return (uint32_t)(row * 128 + ((c ^ (row & 7)) << 4));
}
// swizzled byte offset, [rows][128 bf16] (256B rows)
__device__ __forceinline__ uint32_t swz256(int row, int c)
{
    return (uint32_t)(row * 256 + ((c ^ (row & 7)) << 4));
}

// ---------------------------------------------------------------------------
// Pipelined tensor-core GEMM, fp32 in, in-register bf16 hi/lo split.
// out = A @ W^T, A:[4096,1024], W:[1024,1024].  BM=BN=128, BK=32, 256 thr.
// EPI 0: plain fp32 [M,E]   (output projection -> d_out)
// EPI 1: RoPE(+scale) + hi/lo split -> [B,H,S,DH] bf16 pair   (Q, K)
// EPI 2: fp32 transpose/head-split -> [B,H,S,DH]              (V)
// ---------------------------------------------------------------------------
template <int EPI>
__global__ void __launch_bounds__(256)
gemm_f32(const float* __restrict__ A, const float* __restrict__ W,
         float* __restrict__ outF, __nv_bfloat16* __restrict__ outH,
         __nv_bfloat16* __restrict__ outL, float scale)
{
    __shared__ __align__(16) uint8_t smem[32768];
    constexpr uint32_t oAh = 0, oAl = 8192, oBh = 16384, oBl = 24576;
    const uint32_t sbase = smem_u32(smem);

    const int tid  = threadIdx.x;
    const int warp = tid >> 5, lane = tid & 31;
    const int wm = warp & 3;
    const int wn = warp >> 2;
    const int bx = blockIdx.x, by = blockIdx.y;

    const int lr = tid >> 1, lhalf = tid & 1;
    const float* Ap = A + (size_t)(by * 128 + lr) * E + lhalf * 16;
    const float* Wp = W + (size_t)(bx * 128 + lr) * E + lhalf * 16;
    const uint32_t w0 = swz64(lr, lhalf * 2);
    const uint32_t w1 = swz64(lr, lhalf * 2 + 1);

    uint32_t adA[2][2], adB[4][2];
#pragma unroll
    for (int s = 0; s < 2; s++) {
#pragma unroll
        for (int mt = 0; mt < 2; mt++)
            adA[mt][s] = swz64(wm * 32 + mt * 16 + (lane & 15), s * 2 + (lane >> 4));
#pragma unroll
        for (int g = 0; g < 4; g++)
            adB[g][s] = swz64(wn * 64 + g * 16 + ((lane >> 1) & 8) + (lane & 7),
                              s * 2 + ((lane >> 3) & 1));
    }

    float acc[2][8][4];
#pragma unroll
    for (int mt = 0; mt < 2; mt++)
#pragma unroll
        for (int j = 0; j < 8; j++)
#pragma unroll
            for (int r = 0; r < 4; r++) acc[mt][j][r] = 0.f;

    // prefetch k0 = 0
    float4 ra0 = *reinterpret_cast<const float4*>(Ap);
    float4 ra1 = *reinterpret_cast<const float4*>(Ap + 4);
    float4 ra2 = *reinterpret_cast<const float4*>(Ap + 8);
    float4 ra3 = *reinterpret_cast<const float4*>(Ap + 12);
    float4 rb0 = *reinterpret_cast<const float4*>(Wp);
    float4 rb1 = *reinterpret_cast<const float4*>(Wp + 4);
    float4 rb2 = *reinterpret_cast<const float4*>(Wp + 8);
    float4 rb3 = *reinterpret_cast<const float4*>(Wp + 12);

#pragma unroll 1
    for (int k0 = 0; k0 < E; k0 += 32) {
        uint4 hA0, lA0, hA1, lA1, hB0, lB0, hB1, lB1;
        split8(ra0, ra1, hA0, lA0);
        split8(ra2, ra3, hA1, lA1);
        split8(rb0, rb1, hB0, lB0);
        split8(rb2, rb3, hB1, lB1);
        __syncthreads();   // previous MMA reads complete
        *reinterpret_cast<uint4*>(smem + oAh + w0) = hA0;
        *reinterpret_cast<uint4*>(smem + oAl + w0) = lA0;
        *reinterpret_cast<uint4*>(smem + oAh + w1) = hA1;
        *reinterpret_cast<uint4*>(smem + oAl + w1) = lA1;
        *reinterpret_cast<uint4*>(smem + oBh + w0) = hB0;
        *reinterpret_cast<uint4*>(smem + oBl + w0) = lB0;
        *reinterpret_cast<uint4*>(smem + oBh + w1) = hB1;
        *reinterpret_cast<uint4*>(smem + oBl + w1) = lB1;
        __syncthreads();

        if (k0 + 32 < E) {   // prefetch next tile; overlaps MMA section
            ra0 = *reinterpret_cast<const float4*>(Ap + k0 + 32);
            ra1 = *reinterpret_cast<const float4*>(Ap + k0 + 36);
            ra2 = *reinterpret_cast<const float4*>(Ap + k0 + 40);
            ra3 = *reinterpret_cast<const float4*>(Ap + k0 + 44);
            rb0 = *reinterpret_cast<const float4*>(Wp + k0 + 32);
            rb1 = *reinterpret_cast<const float4*>(Wp + k0 + 36);
            rb2 = *reinterpret_cast<const float4*>(Wp + k0 + 40);
            rb3 = *reinterpret_cast<const float4*>(Wp + k0 + 44);
        }

#pragma unroll
        for (int s = 0; s < 2; s++) {
            uint32_t fAh[2][4], fAl[2][4], fBh[4][4], fBl[4][4];
#pragma unroll
            for (int mt = 0; mt < 2; mt++) {
                ldsm4(fAh[mt], sbase + oAh + adA[mt][s]);
                ldsm4(fAl[mt], sbase + oAl + adA[mt][s]);
            }
#pragma unroll
            for (int g = 0; g < 4; g++) {
                ldsm4(fBh[g], sbase + oBh + adB[g][s]);
                ldsm4(fBl[g], sbase + oBl + adB[g][s]);
            }
#pragma unroll
            for (int mt = 0; mt < 2; mt++)
#pragma unroll
                for (int j = 0; j < 8; j++) {
                    const int g = j >> 1, p = (j & 1) * 2;
                    uint32_t bh[2] = {fBh[g][p], fBh[g][p + 1]};
                    uint32_t bl[2] = {fBl[g][p], fBl[g][p + 1]};
                    mma16816(acc[mt][j], fAh[mt], bh);
                    mma16816(acc[mt][j], fAh[mt], bl);
                    mma16816(acc[mt][j], fAl[mt], bh);
                }
        }
    }

    // ---- epilogues ----
#pragma unroll
    for (int mt = 0; mt < 2; mt++)
#pragma unroll
        for (int j = 0; j < 8; j++) {
            const int m0 = by * 128 + wm * 32 + mt * 16 + (lane >> 2);
            const int n  = bx * 128 + wn * 64 + j * 8 + (lane & 3) * 2;
            if (EPI == 0) {
                *reinterpret_cast<float2*>(outF + (size_t)m0 * E + n) =
                    make_float2(acc[mt][j][0], acc[mt][j][1]);
                *reinterpret_cast<float2*>(outF + (size_t)(m0 + 8) * E + n) =
                    make_float2(acc[mt][j][2], acc[mt][j][3]);
            } else if (EPI == 2) {
                const int hh = (n >> 6) & (H - 1), dd = n & 63;
#pragma unroll
                for (int rr = 0; rr < 2; rr++) {
                    const int m = m0 + rr * 8;
                    const int bb = m >> 11, ss = m & (S - 1);
                    *reinterpret_cast<float2*>(
                        outF + (((size_t)bb * H + hh) * S + ss) * DH + dd) =
                        make_float2(acc[mt][j][rr * 2], acc[mt][j][rr * 2 + 1]);
                }
            } else {   // EPI == 1 : RoPE + scale + hi/lo split
                const int hh = (n >> 6) & (H - 1), dd = n & 63;
                const float invf = g_invfreq[dd >> 1];
#pragma unroll
                for (int rr = 0; rr < 2; rr++) {
                    const int m = m0 + rr * 8;
                    const int bb = m >> 11, ss = m & (S - 1);
                    float sn, cs;
                    sincosf((float)ss * invf, &sn, &cs);
                    const float x = acc[mt][j][rr * 2];
                    const float y = acc[mt][j][rr * 2 + 1];
                    const float rx = (x * cs - y * sn) * scale;
                    const float ry = (y * cs + x * sn) * scale;
                    uint32_t h, l;
                    split2(rx, ry, h, l);
                    const size_t off = (((size_t)bb * H + hh) * S + ss) * DH + dd;
                    *reinterpret_cast<uint32_t*>(outH + off) = h;
                    *reinterpret_cast<uint32_t*>(outL + off) = l;
                }
            }
        }
}

// ---------------------------------------------------------------------------
// V transpose + split: [bh][s][64] fp32 -> [bh][64][s] bf16 hi/lo
// ---------------------------------------------------------------------------
__global__ void __launch_bounds__(256)
vtrans_split(const float* __restrict__ Vf, __nv_bfloat16* __restrict__ hi,
             __nv_bfloat16* __restrict__ lo)
{
    __shared__ float tile[64][65];
    const int tid = threadIdx.x;
    const int s0 = blockIdx.x * 64;
    const int bh = blockIdx.y;

#pragma unroll
    for (int rep = 0; rep < 4; rep++) {
        const int idx = rep * 256 + tid;
        const int r  = idx >> 4;
        const int c4 = (idx & 15) << 2;
        float4 v = *reinterpret_cast<const float4*>(
            Vf + ((size_t)bh * S + s0 + r) * DH + c4);
        tile[c4 + 0][r] = v.x;
        tile[c4 + 1][r] = v.y;
        tile[c4 + 2][r] = v.z;
        tile[c4 + 3][r] = v.w;
    }
    __syncthreads();
#pragma unroll
    for (int rep = 0; rep < 4; rep++) {
        const int idx = rep * 256 + tid;
        const int dh = idx >> 4;
        const int s4 = (idx & 15) << 2;
        uint32_t h0, l0, h1, l1;
        split2(tile[dh][s4], tile[dh][s4 + 1], h0, l0);
        split2(tile[dh][s4 + 2], tile[dh][s4 + 3], h1, l1);
        const size_t off = ((size_t)bh * DH + dh) * S + s0 + s4;
        *reinterpret_cast<uint2*>(hi + off) = make_uint2(h0, h1);
        *reinterpret_cast<uint2*>(lo + off) = make_uint2(l0, l1);
    }
}

// ---------------------------------------------------------------------------
// MMA flash attention (non-causal), bf16 hi/lo split on both GEMMs.
// Grid (S/128, H, B), 256 threads (8 warps); warp w owns q rows [16w,16w+16).
// Epilogue writes fp32 activations [B,S,E] for the output projection.
// ---------------------------------------------------------------------------
constexpr int FA_oQh = 0;
constexpr int FA_oQl = 16384;
constexpr int FA_oKh = 32768;
constexpr int FA_oKl = 49152;
constexpr int FA_oVh = 65536;
constexpr int FA_oVl = 81920;
constexpr int FA_SMEM = 98304;

__global__ void __launch_bounds__(256)
flash_mma(const __nv_bfloat16* __restrict__ Qh, const __nv_bfloat16* __restrict__ Ql,
          const __nv_bfloat16* __restrict__ Kh, const __nv_bfloat16* __restrict__ Kl,
          const __nv_bfloat16* __restrict__ Vth, const __nv_bfloat16* __restrict__ Vtl,
          float* __restrict__ AO)
{
    extern __shared__ __align__(16) uint8_t sm8[];
    const uint32_t sbase = smem_u32(sm8);

    const int tid = threadIdx.x;
    const int warp = tid >> 5, lane = tid & 31;
    const int q0 = blockIdx.x * 128;
    const int hh = blockIdx.y, bb = blockIdx.z;
    const int bh = bb * H + hh;

#pragma unroll
    for (int rep = 0; rep < 4; rep++) {
        const int idx = rep * 256 + tid;
        const int r = idx >> 3, c = idx & 7;
        const size_t go = ((size_t)bh * S + q0 + r) * DH + c * 8;
        const uint32_t so = swz128(r, c);
        *reinterpret_cast<uint4*>(sm8 + FA_oQh + so) =
            *reinterpret_cast<const uint4*>(Qh + go);
        *reinterpret_cast<uint4*>(sm8 + FA_oQl + so) =
            *reinterpret_cast<const uint4*>(Ql + go);
    }

    float m_run[2] = {-1e30f, -1e30f};
    float l_run[2] = {0.f, 0.f};
    float o[8][4];
#pragma unroll
    for (int j = 0; j < 8; j++)
#pragma unroll
        for (int r = 0; r < 4; r++) o[j][r] = 0.f;

    const int aQrow = warp * 16 + (lane & 15);
    const int aQcs  = lane >> 4;
    const int bRow8 = ((lane >> 1) & 8) + (lane & 7);
    const int bCs   = (lane >> 3) & 1;

#pragma unroll 1
    for (int t = 0; t < S / 128; t++) {
        __syncthreads();
#pragma unroll
        for (int rep = 0; rep < 4; rep++) {
            const int idx = rep * 256 + tid;
            {
                const int r = idx >> 3, c = idx & 7;
                const size_t go = ((size_t)bh * S + t * 128 + r) * DH + c * 8;
                const uint32_t so = swz128(r, c);
                *reinterpret_cast<uint4*>(sm8 + FA_oKh + so) =
                    *reinterpret_cast<const uint4*>(Kh + go);
                *reinterpret_cast<uint4*>(sm8 + FA_oKl + so) =
                    *reinterpret_cast<const uint4*>(Kl + go);
            }
            {
                const int r = idx >> 4, c = idx & 15;
                const size_t go = ((size_t)bh * DH + r) * S + t * 128 + c * 8;
                const uint32_t so = swz256(r, c);
                *reinterpret_cast<uint4*>(sm8 + FA_oVh + so) =
                    *reinterpret_cast<const uint4*>(Vth + go);
                *reinterpret_cast<uint4*>(sm8 + FA_oVl + so) =
                    *reinterpret_cast<const uint4*>(Vtl + go);
            }
        }
        __syncthreads();

        float acc[16][4];
#pragma unroll
        for (int j = 0; j < 16; j++)
#pragma unroll
            for (int r = 0; r < 4; r++) acc[j][r] = 0.f;

#pragma unroll
        for (int s = 0; s < 4; s++) {
            uint32_t ah[4], al[4];
            const uint32_t qoff = swz128(aQrow, 2 * s + aQcs);
            ldsm4(ah, sbase + FA_oQh + qoff);
            ldsm4(al, sbase + FA_oQl + qoff);
#pragma unroll
            for (int g = 0; g < 8; g++) {
                const uint32_t koff = swz128(g * 16 + bRow8, 2 * s + bCs);
                uint32_t kbh[4], kbl[4];
                ldsm4(kbh, sbase + FA_oKh + koff);
                ldsm4(kbl, sbase + FA_oKl + koff);
#pragma unroll
                for (int jj = 0; jj < 2; jj++) {
                    const int j = g * 2 + jj, p = jj * 2;
                    uint32_t bH[2] = {kbh[p], kbh[p + 1]};
                    uint32_t bL[2] = {kbl[p], kbl[p + 1]};
                    mma16816(acc[j], ah, bH);
                    mma16816(acc[j], ah, bL);
                    mma16816(acc[j], al, bH);
                }
            }
        }

#pragma unroll
        for (int rh = 0; rh < 2; rh++) {
            const int c0 = rh * 2, c1 = rh * 2 + 1;
            float mx = acc[0][c0];
#pragma unroll
            for (int j = 0; j < 16; j++)
                mx = fmaxf(mx, fmaxf(acc[j][c0], acc[j][c1]));
            mx = fmaxf(mx, __shfl_xor_sync(0xffffffffu, mx, 1));
            mx = fmaxf(mx, __shfl_xor_sync(0xffffffffu, mx, 2));
            const float newm = fmaxf(m_run[rh], mx);
            const float corr = __expf(m_run[rh] - newm);
            m_run[rh] = newm;
            float ls = 0.f;
#pragma unroll
            for (int j = 0; j < 16; j++) {
                acc[j][c0] = __expf(acc[j][c0] - newm);
                acc[j][c1] = __expf(acc[j][c1] - newm);
                ls += acc[j][c0] + acc[j][c1];
            }
            ls += __shfl_xor_sync(0xffffffffu, ls, 1);
            ls += __shfl_xor_sync(0xffffffffu, ls, 2);
            l_run[rh] = l_run[rh] * corr + ls;
#pragma unroll
            for (int j = 0; j < 8; j++) {
                o[j][c0] *= corr;
                o[j][c1] *= corr;
            }
        }

#pragma unroll
        for (int s = 0; s < 8; s++) {
            uint32_t pah[4], pal[4];
            split2(acc[2 * s][0], acc[2 * s][1], pah[0], pal[0]);
            split2(acc[2 * s][2], acc[2 * s][3], pah[1], pal[1]);
            split2(acc[2 * s + 1][0], acc[2 * s + 1][1], pah[2], pal[2]);
            split2(acc[2 * s + 1][2], acc[2 * s + 1][3], pah[3], pal[3]);
#pragma unroll
            for (int ng = 0; ng < 4; ng++) {
                const uint32_t voff = swz256(ng * 16 + bRow8, 2 * s + bCs);
                uint32_t vbh[4], vbl[4];
                ldsm4(vbh, sbase + FA_oVh + voff);
                ldsm4(vbl, sbase + FA_oVl + voff);
#pragma unroll
                for (int jj = 0; jj < 2; jj++) {
                    const int j = ng * 2 + jj, p = jj * 2;
                    uint32_t bH[2] = {vbh[p], vbh[p + 1]};
                    uint32_t bL[2] = {vbl[p], vbl[p + 1]};
                    mma16816(o[j], pah, bH);
                    mma16816(o[j], pah, bL);
                    mma16816(o[j], pal, bH);
                }
            }
        }
    }

    // epilogue: normalize, write fp32 activations [B,S,E]
    const float inv0 = 1.f / l_run[0];
    const float inv1 = 1.f / l_run[1];
    const int r0 = q0 + warp * 16 + (lane >> 2);
    const int r1 = r0 + 8;
#pragma unroll
    for (int j = 0; j < 8; j++) {
        const int col = hh * 64 + j * 8 + (lane & 3) * 2;
        *reinterpret_cast<float2*>(AO + ((size_t)bb * S + r0) * E + col) =
            make_float2(o[j][0] * inv0, o[j][1] * inv0);
        *reinterpret_cast<float2*>(AO + ((size_t)bb * S + r1) * E + col) =
            make_float2(o[j][2] * inv1, o[j][3] * inv1);
    }
}

// ---------------------------------------------------------------------------
extern "C" void kernel_launch(void* const* d_in, const int* in_sizes, int n_in,
                              void* d_out, int out_size)
{
    const float* q  = (const float*)d_in[0];
    const float* k  = (const float*)d_in[1];
    const float* v  = (const float*)d_in[2];
    const float* Wq = (const float*)d_in[3];
    const float* Wk = (const float*)d_in[4];
    const float* Wv = (const float*)d_in[5];
    const float* Wo = (const float*)d_in[6];
    float* out = (float*)d_out;

    float *pV, *pAO;
    __nv_bfloat16 *qh, *ql, *kh, *kl, *vth, *vtl;
    cudaGetSymbolAddress((void**)&pV,  g_V);
    cudaGetSymbolAddress((void**)&pAO, g_AO);
    cudaGetSymbolAddress((void**)&qh,  g_Qh);
    cudaGetSymbolAddress((void**)&ql,  g_Ql);
    cudaGetSymbolAddress((void**)&kh,  g_Kh);
    cudaGetSymbolAddress((void**)&kl,  g_Kl);
    cudaGetSymbolAddress((void**)&vth, g_Vth);
    cudaGetSymbolAddress((void**)&vtl, g_Vtl);

    cudaFuncSetAttribute(flash_mma,
                         cudaFuncAttributeMaxDynamicSharedMemorySize, FA_SMEM);

    init_invfreq_kernel<<<1, 32>>>();

    dim3 gg(E / 128, M_TOT / 128);   // (8, 32)

    gemm_f32<1><<<gg, 256>>>(q, Wq, nullptr, qh, ql, 0.03125f);  // RoPE+1/sqrt(E)
    gemm_f32<1><<<gg, 256>>>(k, Wk, nullptr, kh, kl, 1.0f);      // RoPE
    gemm_f32<2><<<gg, 256>>>(v, Wv, pV, nullptr, nullptr, 0.f);  // V fp32 trans

    vtrans_split<<<dim3(S / 64, B * H), 256>>>(pV, vth, vtl);

    dim3 ag(S / 128, H, B);
    flash_mma<<<ag, 256, FA_SMEM>>>(qh, ql, kh, kl, vth, vtl, pAO);

    gemm_f32<0><<<gg, 256>>>(pAO, Wo, out, nullptr, nullptr, 0.f);
}

// round 6
// speedup vs baseline: 3.8502x; 1.1830x over previous
#include <cuda_runtime.h>
#include <cuda_bf16.h>
#include <math.h>
#include <stdint.h>

// Problem constants
constexpr int B  = 2;
constexpr int S  = 2048;
constexpr int E  = 1024;
constexpr int H  = 16;
constexpr int DH = 64;
constexpr int M_TOT = B * S;          // 4096

// Scratch (allocation-free rule: __device__ globals)
__device__ float g_invfreq[32];
__device__ __nv_bfloat16 g_aH[(size_t)M_TOT * E];
__device__ __nv_bfloat16 g_aL[(size_t)M_TOT * E];
__device__ __nv_bfloat16 g_wH[(size_t)E * E];
__device__ __nv_bfloat16 g_wL[(size_t)E * E];
__device__ __nv_bfloat16 g_Qh[(size_t)B * H * S * DH];
__device__ __nv_bfloat16 g_Ql[(size_t)B * H * S * DH];
__device__ __nv_bfloat16 g_Kh[(size_t)B * H * S * DH];
__device__ __nv_bfloat16 g_Kl[(size_t)B * H * S * DH];
__device__ __nv_bfloat16 g_Vth[(size_t)B * H * DH * S];  // [bh][dh][s]
__device__ __nv_bfloat16 g_Vtl[(size_t)B * H * DH * S];

// ---------------------------------------------------------------------------
__global__ void init_invfreq_kernel()
{
    const int i = threadIdx.x;
    g_invfreq[i] = (float)pow(10000.0, -(double)(2 * i) / 64.0);
}

// ---------------------------------------------------------------------------
// helpers
// ---------------------------------------------------------------------------
__device__ __forceinline__ uint32_t smem_u32(const void* p)
{
    uint32_t a;
    asm("{ .reg .u64 t; cvta.to.shared.u64 t, %1; cvt.u32.u64 %0, t; }"
        : "=r"(a) : "l"(p));
    return a;
}
__device__ __forceinline__ void ldsm4(uint32_t* r, uint32_t addr)
{
    asm volatile("ldmatrix.sync.aligned.m8n8.x4.shared.b16 {%0,%1,%2,%3}, [%4];"
                 : "=r"(r[0]), "=r"(r[1]), "=r"(r[2]), "=r"(r[3]) : "r"(addr));
}
__device__ __forceinline__ void mma16816(float* c, const uint32_t* a,
                                         const uint32_t* b)
{
    asm volatile("mma.sync.aligned.m16n8k16.row.col.f32.bf16.bf16.f32 "
                 "{%0,%1,%2,%3}, {%4,%5,%6,%7}, {%8,%9}, {%0,%1,%2,%3};"
                 : "+f"(c[0]), "+f"(c[1]), "+f"(c[2]), "+f"(c[3])
                 : "r"(a[0]), "r"(a[1]), "r"(a[2]), "r"(a[3]),
                   "r"(b[0]), "r"(b[1]));
}
__device__ __forceinline__ void split2(float x, float y, uint32_t& h, uint32_t& l)
{
    __nv_bfloat16 hx = __float2bfloat16(x), hy = __float2bfloat16(y);
    __nv_bfloat16 lx = __float2bfloat16(x - __bfloat162float(hx));
    __nv_bfloat16 ly = __float2bfloat16(y - __bfloat162float(hy));
    __nv_bfloat162 hp{hx, hy}, lp{lx, ly};
    h = *reinterpret_cast<uint32_t*>(&hp);
    l = *reinterpret_cast<uint32_t*>(&lp);
}
__device__ __forceinline__ void cp16(uint32_t dst, const void* src)
{
    asm volatile("cp.async.cg.shared.global [%0], [%1], 16;"
                 :: "r"(dst), "l"(src));
}
__device__ __forceinline__ void cp_commit()
{
    asm volatile("cp.async.commit_group;");
}
__device__ __forceinline__ void cp_wait0()
{
    asm volatile("cp.async.wait_group 0;");
}
// swizzled byte offset, [rows][32 bf16] (64B rows)
__device__ __forceinline__ uint32_t swz64(int row, int c)
{
    return (uint32_t)(row * 64 + ((c ^ ((row >> 1) & 3)) << 4));
}
// swizzled byte offset, [rows][64 bf16] (128B rows)
__device__ __forceinline__ uint32_t swz128(int row, int c)
{
    return (uint32_t)(row * 128 + ((c ^ (row & 7)) << 4));
}
// swizzled byte offset, [rows][128 bf16] (256B rows)
__device__ __forceinline__ uint32_t swz256(int row, int c)
{
    return (uint32_t)(row * 256 + ((c ^ (row & 7)) << 4));
}

// ---------------------------------------------------------------------------
// fp32 -> bf16 hi/lo split (standalone; ~free, memory-bound)
// ---------------------------------------------------------------------------
__global__ void __launch_bounds__(256)
convert_split(const float* __restrict__ x, __nv_bfloat16* __restrict__ hi,
              __nv_bfloat16* __restrict__ lo, int n4)
{
    const int i = blockIdx.x * blockDim.x + threadIdx.x;
    if (i >= n4) return;
    float4 v = reinterpret_cast<const float4*>(x)[i];
    uint2 hu, lu;
    split2(v.x, v.y, hu.x, lu.x);
    split2(v.z, v.w, hu.y, lu.y);
    *reinterpret_cast<uint2*>(hi + 4 * (size_t)i) = hu;
    *reinterpret_cast<uint2*>(lo + 4 * (size_t)i) = lu;
}

// ---------------------------------------------------------------------------
// Double-buffered cp.async tensor-core GEMM, bf16 hi/lo inputs.
// out = A @ W^T.  BM=BN=128, BK=32, 256 thr, 2-stage smem (64KB), 2 CTAs/SM.
// EPI 0: fp32 [M,E]                       (output projection -> d_out)
// EPI 1: RoPE(+scale) + split -> [B,H,S,DH] bf16 pair        (Q, K)
// EPI 2: transpose + split -> [B*H, DH, S] bf16 pair          (V)
// ---------------------------------------------------------------------------
constexpr int GE_STAGE = 32768;   // oAh=0, oAl=8192, oBh=16384, oBl=24576
constexpr int GE_SMEM  = 2 * GE_STAGE;

template <int EPI>
__global__ void __launch_bounds__(256, 2)
gemm_bf(const __nv_bfloat16* __restrict__ Ahg, const __nv_bfloat16* __restrict__ Alg,
        const __nv_bfloat16* __restrict__ Bhg, const __nv_bfloat16* __restrict__ Blg,
        float* __restrict__ outF, __nv_bfloat16* __restrict__ outH,
        __nv_bfloat16* __restrict__ outL, float scale)
{
    extern __shared__ __align__(128) uint8_t smem[];
    const uint32_t sb = smem_u32(smem);

    const int tid  = threadIdx.x;
    const int warp = tid >> 5, lane = tid & 31;
    const int wm = warp & 3;
    const int wn = warp >> 2;
    const int bx = blockIdx.x, by = blockIdx.y;

    const int lr = tid >> 1, lhalf = tid & 1;
    const __nv_bfloat16* pAh = Ahg + (size_t)(by * 128 + lr) * E + lhalf * 16;
    const __nv_bfloat16* pAl = Alg + (size_t)(by * 128 + lr) * E + lhalf * 16;
    const __nv_bfloat16* pBh = Bhg + (size_t)(bx * 128 + lr) * E + lhalf * 16;
    const __nv_bfloat16* pBl = Blg + (size_t)(bx * 128 + lr) * E + lhalf * 16;
    const uint32_t w0 = swz64(lr, lhalf * 2);
    const uint32_t w1 = swz64(lr, lhalf * 2 + 1);

    uint32_t adA[2][2], adB[4][2];
#pragma unroll
    for (int s = 0; s < 2; s++) {
#pragma unroll
        for (int mt = 0; mt < 2; mt++)
            adA[mt][s] = swz64(wm * 32 + mt * 16 + (lane & 15), s * 2 + (lane >> 4));
#pragma unroll
        for (int g = 0; g < 4; g++)
            adB[g][s] = swz64(wn * 64 + g * 16 + ((lane >> 1) & 8) + (lane & 7),
                              s * 2 + ((lane >> 3) & 1));
    }

    float acc[2][8][4];
#pragma unroll
    for (int mt = 0; mt < 2; mt++)
#pragma unroll
        for (int j = 0; j < 8; j++)
#pragma unroll
            for (int r = 0; r < 4; r++) acc[mt][j][r] = 0.f;

    // prologue: stage 0 <- k0 = 0
    {
        const uint32_t s0 = sb;
        cp16(s0 +     0 + w0, pAh);      cp16(s0 +     0 + w1, pAh + 8);
        cp16(s0 +  8192 + w0, pAl);      cp16(s0 +  8192 + w1, pAl + 8);
        cp16(s0 + 16384 + w0, pBh);      cp16(s0 + 16384 + w1, pBh + 8);
        cp16(s0 + 24576 + w0, pBl);      cp16(s0 + 24576 + w1, pBl + 8);
        cp_commit();
    }

#pragma unroll 1
    for (int k0 = 0; k0 < E; k0 += 32) {
        const int st = (k0 >> 5) & 1;
        cp_wait0();
        __syncthreads();   // tile k0 arrived; all reads of other stage done
        if (k0 + 32 < E) {
            const uint32_t s1 = sb + (st ^ 1) * GE_STAGE;
            const int kn = k0 + 32;
            cp16(s1 +     0 + w0, pAh + kn);  cp16(s1 +     0 + w1, pAh + kn + 8);
            cp16(s1 +  8192 + w0, pAl + kn);  cp16(s1 +  8192 + w1, pAl + kn + 8);
            cp16(s1 + 16384 + w0, pBh + kn);  cp16(s1 + 16384 + w1, pBh + kn + 8);
            cp16(s1 + 24576 + w0, pBl + kn);  cp16(s1 + 24576 + w1, pBl + kn + 8);
            cp_commit();
        }
        const uint32_t sg = sb + st * GE_STAGE;

#pragma unroll
        for (int s = 0; s < 2; s++) {
            uint32_t fAh[2][4], fAl[2][4], fBh[4][4], fBl[4][4];
#pragma unroll
            for (int mt = 0; mt < 2; mt++) {
                ldsm4(fAh[mt], sg +     0 + adA[mt][s]);
                ldsm4(fAl[mt], sg +  8192 + adA[mt][s]);
            }
#pragma unroll
            for (int g = 0; g < 4; g++) {
                ldsm4(fBh[g], sg + 16384 + adB[g][s]);
                ldsm4(fBl[g], sg + 24576 + adB[g][s]);
            }
#pragma unroll
            for (int mt = 0; mt < 2; mt++)
#pragma unroll
                for (int j = 0; j < 8; j++) {
                    const int g = j >> 1, p = (j & 1) * 2;
                    uint32_t bh[2] = {fBh[g][p], fBh[g][p + 1]};
                    uint32_t bl[2] = {fBl[g][p], fBl[g][p + 1]};
                    mma16816(acc[mt][j], fAh[mt], bh);
                    mma16816(acc[mt][j], fAh[mt], bl);
                    mma16816(acc[mt][j], fAl[mt], bh);
                }
        }
    }

    // ---- epilogues ----
#pragma unroll
    for (int mt = 0; mt < 2; mt++)
#pragma unroll
        for (int j = 0; j < 8; j++) {
            const int m0 = by * 128 + wm * 32 + mt * 16 + (lane >> 2);
            const int n  = bx * 128 + wn * 64 + j * 8 + (lane & 3) * 2;
            if (EPI == 0) {
                *reinterpret_cast<float2*>(outF + (size_t)m0 * E + n) =
                    make_float2(acc[mt][j][0], acc[mt][j][1]);
                *reinterpret_cast<float2*>(outF + (size_t)(m0 + 8) * E + n) =
                    make_float2(acc[mt][j][2], acc[mt][j][3]);
            } else if (EPI == 2) {
                // transpose + split: Vt[bh][dh][s]
                const int hh = (n >> 6) & (H - 1), dd = n & 63;
#pragma unroll
                for (int rr = 0; rr < 2; rr++) {
                    const int m = m0 + rr * 8;
                    const int bb = m >> 11, ss = m & (S - 1);
                    const size_t base = ((size_t)(bb * H + hh) * DH + dd) * S + ss;
                    const float x = acc[mt][j][rr * 2];
                    const float y = acc[mt][j][rr * 2 + 1];
                    __nv_bfloat16 hx = __float2bfloat16(x);
                    __nv_bfloat16 lx = __float2bfloat16(x - __bfloat162float(hx));
                    __nv_bfloat16 hy = __float2bfloat16(y);
                    __nv_bfloat16 ly = __float2bfloat16(y - __bfloat162float(hy));
                    outH[base]     = hx;
                    outL[base]     = lx;
                    outH[base + S] = hy;   // dd+1 row
                    outL[base + S] = ly;
                }
            } else {   // EPI == 1 : RoPE + scale + hi/lo split
                const int hh = (n >> 6) & (H - 1), dd = n & 63;
                const float invf = g_invfreq[dd >> 1];
#pragma unroll
                for (int rr = 0; rr < 2; rr++) {
                    const int m = m0 + rr * 8;
                    const int bb = m >> 11, ss = m & (S - 1);
                    float sn, cs;
                    sincosf((float)ss * invf, &sn, &cs);
                    const float x = acc[mt][j][rr * 2];
                    const float y = acc[mt][j][rr * 2 + 1];
                    const float rx = (x * cs - y * sn) * scale;
                    const float ry = (y * cs + x * sn) * scale;
                    uint32_t h, l;
                    split2(rx, ry, h, l);
                    const size_t off = (((size_t)bb * H + hh) * S + ss) * DH + dd;
                    *reinterpret_cast<uint32_t*>(outH + off) = h;
                    *reinterpret_cast<uint32_t*>(outL + off) = l;
                }
            }
        }
}

// ---------------------------------------------------------------------------
// MMA flash attention, bf16 hi/lo split, cp.async double-buffered K/V.
// Grid (S/128, H, B), 256 threads (8 warps); warp w owns q rows [16w,16w+16).
// smem: Q hi/lo 32KB + 2 stages x (Kh,Kl,Vh,Vl = 64KB) = 160KB.
// Epilogue writes split bf16 activations [B,S,E] for the output projection.
// ---------------------------------------------------------------------------
constexpr int FA_STAGE0 = 32768;   // after Qh(16K)+Ql(16K)
constexpr int FA_STAGE  = 65536;   // Kh 0, Kl 16384, Vh 32768, Vl 49152
constexpr int FA_SMEM   = FA_STAGE0 + 2 * FA_STAGE;  // 163840

__global__ void __launch_bounds__(256)
flash_mma(const __nv_bfloat16* __restrict__ Qh, const __nv_bfloat16* __restrict__ Ql,
          const __nv_bfloat16* __restrict__ Kh, const __nv_bfloat16* __restrict__ Kl,
          const __nv_bfloat16* __restrict__ Vth, const __nv_bfloat16* __restrict__ Vtl,
          __nv_bfloat16* __restrict__ aH, __nv_bfloat16* __restrict__ aL)
{
    extern __shared__ __align__(128) uint8_t sm8[];
    const uint32_t sb = smem_u32(sm8);

    const int tid = threadIdx.x;
    const int warp = tid >> 5, lane = tid & 31;
    const int q0 = blockIdx.x * 128;
    const int hh = blockIdx.y, bb = blockIdx.z;
    const int bh = bb * H + hh;

    // load Q tile hi/lo ([128][64] bf16, swizzled 128B rows)
#pragma unroll
    for (int rep = 0; rep < 4; rep++) {
        const int idx = rep * 256 + tid;
        const int r = idx >> 3, c = idx & 7;
        const size_t go = ((size_t)bh * S + q0 + r) * DH + c * 8;
        const uint32_t so = swz128(r, c);
        *reinterpret_cast<uint4*>(sm8 + so) =
            *reinterpret_cast<const uint4*>(Qh + go);
        *reinterpret_cast<uint4*>(sm8 + 16384 + so) =
            *reinterpret_cast<const uint4*>(Ql + go);
    }

    // prologue: stage 0 <- tile 0
    {
        const uint32_t sg = sb + FA_STAGE0;
#pragma unroll
        for (int rep = 0; rep < 4; rep++) {
            const int idx = rep * 256 + tid;
            {
                const int r = idx >> 3, c = idx & 7;
                const size_t go = ((size_t)bh * S + r) * DH + c * 8;
                const uint32_t so = swz128(r, c);
                cp16(sg + so,         Kh + go);
                cp16(sg + 16384 + so, Kl + go);
            }
            {
                const int r = idx >> 4, c = idx & 15;
                const size_t go = ((size_t)bh * DH + r) * S + c * 8;
                const uint32_t so = swz256(r, c);
                cp16(sg + 32768 + so, Vth + go);
                cp16(sg + 49152 + so, Vtl + go);
            }
        }
        cp_commit();
    }

    float m_run[2] = {-1e30f, -1e30f};
    float l_run[2] = {0.f, 0.f};
    float o[8][4];
#pragma unroll
    for (int j = 0; j < 8; j++)
#pragma unroll
        for (int r = 0; r < 4; r++) o[j][r] = 0.f;

    const int aQrow = warp * 16 + (lane & 15);
    const int aQcs  = lane >> 4;
    const int bRow8 = ((lane >> 1) & 8) + (lane & 7);
    const int bCs   = (lane >> 3) & 1;

#pragma unroll 1
    for (int t = 0; t < S / 128; t++) {
        cp_wait0();
        __syncthreads();   // tile t arrived; prior reads of other stage done
        if (t + 1 < S / 128) {
            const uint32_t sg = sb + FA_STAGE0 + ((t + 1) & 1) * FA_STAGE;
#pragma unroll
            for (int rep = 0; rep < 4; rep++) {
                const int idx = rep * 256 + tid;
                {
                    const int r = idx >> 3, c = idx & 7;
                    const size_t go = ((size_t)bh * S + (t + 1) * 128 + r) * DH + c * 8;
                    const uint32_t so = swz128(r, c);
                    cp16(sg + so,         Kh + go);
                    cp16(sg + 16384 + so, Kl + go);
                }
                {
                    const int r = idx >> 4, c = idx & 15;
                    const size_t go = ((size_t)bh * DH + r) * S + (t + 1) * 128 + c * 8;
                    const uint32_t so = swz256(r, c);
                    cp16(sg + 32768 + so, Vth + go);
                    cp16(sg + 49152 + so, Vtl + go);
                }
            }
            cp_commit();
        }
        const uint32_t sg = sb + FA_STAGE0 + (t & 1) * FA_STAGE;

        // ---- S = Q K^T ----
        float acc[16][4];
#pragma unroll
        for (int j = 0; j < 16; j++)
#pragma unroll
            for (int r = 0; r < 4; r++) acc[j][r] = 0.f;

#pragma unroll
        for (int s = 0; s < 4; s++) {
            uint32_t ah[4], al[4];
            const uint32_t qoff = swz128(aQrow, 2 * s + aQcs);
            ldsm4(ah, sb + qoff);
            ldsm4(al, sb + 16384 + qoff);
#pragma unroll
            for (int g = 0; g < 8; g++) {
                const uint32_t koff = swz128(g * 16 + bRow8, 2 * s + bCs);
                uint32_t kbh[4], kbl[4];
                ldsm4(kbh, sg + koff);
                ldsm4(kbl, sg + 16384 + koff);
#pragma unroll
                for (int jj = 0; jj < 2; jj++) {
                    const int j = g * 2 + jj, p = jj * 2;
                    uint32_t bH[2] = {kbh[p], kbh[p + 1]};
                    uint32_t bL[2] = {kbl[p], kbl[p + 1]};
                    mma16816(acc[j], ah, bH);
                    mma16816(acc[j], ah, bL);
                    mma16816(acc[j], al, bH);
                }
            }
        }

        // ---- online softmax (quad shuffles) ----
#pragma unroll
        for (int rh = 0; rh < 2; rh++) {
            const int c0 = rh * 2, c1 = rh * 2 + 1;
            float mx = acc[0][c0];
#pragma unroll
            for (int j = 0; j < 16; j++)
                mx = fmaxf(mx, fmaxf(acc[j][c0], acc[j][c1]));
            mx = fmaxf(mx, __shfl_xor_sync(0xffffffffu, mx, 1));
            mx = fmaxf(mx, __shfl_xor_sync(0xffffffffu, mx, 2));
            const float newm = fmaxf(m_run[rh], mx);
            const float corr = __expf(m_run[rh] - newm);
            m_run[rh] = newm;
            float ls = 0.f;
#pragma unroll
            for (int j = 0; j < 16; j++) {
                acc[j][c0] = __expf(acc[j][c0] - newm);
                acc[j][c1] = __expf(acc[j][c1] - newm);
                ls += acc[j][c0] + acc[j][c1];
            }
            ls += __shfl_xor_sync(0xffffffffu, ls, 1);
            ls += __shfl_xor_sync(0xffffffffu, ls, 2);
            l_run[rh] = l_run[rh] * corr + ls;
#pragma unroll
            for (int j = 0; j < 8; j++) {
                o[j][c0] *= corr;
                o[j][c1] *= corr;
            }
        }

        // ---- O += P V ----
#pragma unroll
        for (int s = 0; s < 8; s++) {
            uint32_t pah[4], pal[4];
            split2(acc[2 * s][0], acc[2 * s][1], pah[0], pal[0]);
            split2(acc[2 * s][2], acc[2 * s][3], pah[1], pal[1]);
            split2(acc[2 * s + 1][0], acc[2 * s + 1][1], pah[2], pal[2]);
            split2(acc[2 * s + 1][2], acc[2 * s + 1][3], pah[3], pal[3]);
#pragma unroll
            for (int ng = 0; ng < 4; ng++) {
                const uint32_t voff = swz256(ng * 16 + bRow8, 2 * s + bCs);
                uint32_t vbh[4], vbl[4];
                ldsm4(vbh, sg + 32768 + voff);
                ldsm4(vbl, sg + 49152 + voff);
#pragma unroll
                for (int jj = 0; jj < 2; jj++) {
                    const int j = ng * 2 + jj, p = jj * 2;
                    uint32_t bH[2] = {vbh[p], vbh[p + 1]};
                    uint32_t bL[2] = {vbl[p], vbl[p + 1]};
                    mma16816(o[j], pah, bH);
                    mma16816(o[j], pah, bL);
                    mma16816(o[j], pal, bH);
                }
            }
        }
    }

    // epilogue: normalize, split, write bf16 activations [B,S,E]
    const float inv0 = 1.f / l_run[0];
    const float inv1 = 1.f / l_run[1];
    const int r0 = q0 + warp * 16 + (lane >> 2);
    const int r1 = r0 + 8;
#pragma unroll
    for (int j = 0; j < 8; j++) {
        const int col = hh * 64 + j * 8 + (lane & 3) * 2;
        const size_t off0 = ((size_t)bb * S + r0) * E + col;
        const size_t off1 = ((size_t)bb * S + r1) * E + col;
        uint32_t h, l;
        split2(o[j][0] * inv0, o[j][1] * inv0, h, l);
        *reinterpret_cast<uint32_t*>(aH + off0) = h;
        *reinterpret_cast<uint32_t*>(aL + off0) = l;
        split2(o[j][2] * inv1, o[j][3] * inv1, h, l);
        *reinterpret_cast<uint32_t*>(aH + off1) = h;
        *reinterpret_cast<uint32_t*>(aL + off1) = l;
    }
}

// ---------------------------------------------------------------------------
extern "C" void kernel_launch(void* const* d_in, const int* in_sizes, int n_in,
                              void* d_out, int out_size)
{
    const float* q  = (const float*)d_in[0];
    const float* k  = (const float*)d_in[1];
    const float* v  = (const float*)d_in[2];
    const float* Wq = (const float*)d_in[3];
    const float* Wk = (const float*)d_in[4];
    const float* Wv = (const float*)d_in[5];
    const float* Wo = (const float*)d_in[6];
    float* out = (float*)d_out;

    __nv_bfloat16 *aH, *aL, *wH, *wL, *qh, *ql, *kh, *kl, *vth, *vtl;
    cudaGetSymbolAddress((void**)&aH,  g_aH);
    cudaGetSymbolAddress((void**)&aL,  g_aL);
    cudaGetSymbolAddress((void**)&wH,  g_wH);
    cudaGetSymbolAddress((void**)&wL,  g_wL);
    cudaGetSymbolAddress((void**)&qh,  g_Qh);
    cudaGetSymbolAddress((void**)&ql,  g_Ql);
    cudaGetSymbolAddress((void**)&kh,  g_Kh);
    cudaGetSymbolAddress((void**)&kl,  g_Kl);
    cudaGetSymbolAddress((void**)&vth, g_Vth);
    cudaGetSymbolAddress((void**)&vtl, g_Vtl);

    cudaFuncSetAttribute(gemm_bf<0>,
                         cudaFuncAttributeMaxDynamicSharedMemorySize, GE_SMEM);
    cudaFuncSetAttribute(gemm_bf<1>,
                         cudaFuncAttributeMaxDynamicSharedMemorySize, GE_SMEM);
    cudaFuncSetAttribute(gemm_bf<2>,
                         cudaFuncAttributeMaxDynamicSharedMemorySize, GE_SMEM);
    cudaFuncSetAttribute(flash_mma,
                         cudaFuncAttributeMaxDynamicSharedMemorySize, FA_SMEM);

    init_invfreq_kernel<<<1, 32>>>();

    constexpr int NA4 = M_TOT * E / 4;
    constexpr int NW4 = E * E / 4;
    dim3 gg(E / 128, M_TOT / 128);   // (8, 32)

    convert_split<<<NW4 / 256, 256>>>(Wq, wH, wL, NW4);
    convert_split<<<NA4 / 256, 256>>>(q, aH, aL, NA4);
    gemm_bf<1><<<gg, 256, GE_SMEM>>>(aH, aL, wH, wL, nullptr, qh, ql, 0.03125f);

    convert_split<<<NW4 / 256, 256>>>(Wk, wH, wL, NW4);
    convert_split<<<NA4 / 256, 256>>>(k, aH, aL, NA4);
    gemm_bf<1><<<gg, 256, GE_SMEM>>>(aH, aL, wH, wL, nullptr, kh, kl, 1.0f);

    convert_split<<<NW4 / 256, 256>>>(Wv, wH, wL, NW4);
    convert_split<<<NA4 / 256, 256>>>(v, aH, aL, NA4);
    gemm_bf<2><<<gg, 256, GE_SMEM>>>(aH, aL, wH, wL, nullptr, vth, vtl, 0.f);

    dim3 ag(S / 128, H, B);
    flash_mma<<<ag, 256, FA_SMEM>>>(qh, ql, kh, kl, vth, vtl, aH, aL);

    convert_split<<<NW4 / 256, 256>>>(Wo, wH, wL, NW4);
    gemm_bf<0><<<gg, 256, GE_SMEM>>>(aH, aL, wH, wL, out, nullptr, nullptr, 0.f);
}

// round 8
// speedup vs baseline: 3.9382x; 1.0229x over previous
#include <cuda_runtime.h>
#include <cuda_bf16.h>
#include <math.h>
#include <stdint.h>

// Problem constants
constexpr int B  = 2;
constexpr int S  = 2048;
constexpr int E  = 1024;
constexpr int H  = 16;
constexpr int DH = 64;
constexpr int M_TOT = B * S;          // 4096
constexpr int NA4 = M_TOT * E / 4;    // 1048576 float4 per activation
constexpr int NW4 = E * E / 4;        // 262144 float4 per weight

// Scratch (allocation-free rule: __device__ globals)
__device__ float g_invfreq[32];
__device__ __nv_bfloat16 g_aqH[(size_t)M_TOT * E], g_aqL[(size_t)M_TOT * E];
__device__ __nv_bfloat16 g_akH[(size_t)M_TOT * E], g_akL[(size_t)M_TOT * E];
__device__ __nv_bfloat16 g_avH[(size_t)M_TOT * E], g_avL[(size_t)M_TOT * E];
__device__ __nv_bfloat16 g_wqH[(size_t)E * E], g_wqL[(size_t)E * E];
__device__ __nv_bfloat16 g_wkH[(size_t)E * E], g_wkL[(size_t)E * E];
__device__ __nv_bfloat16 g_wvH[(size_t)E * E], g_wvL[(size_t)E * E];
__device__ __nv_bfloat16 g_woH[(size_t)E * E], g_woL[(size_t)E * E];
__device__ __nv_bfloat16 g_Qh[(size_t)B * H * S * DH], g_Ql[(size_t)B * H * S * DH];
__device__ __nv_bfloat16 g_Kh[(size_t)B * H * S * DH], g_Kl[(size_t)B * H * S * DH];
__device__ __nv_bfloat16 g_Vth[(size_t)B * H * DH * S], g_Vtl[(size_t)B * H * DH * S];

// ---------------------------------------------------------------------------
__global__ void init_invfreq_kernel()
{
    const int i = threadIdx.x;
    g_invfreq[i] = (float)pow(10000.0, -(double)(2 * i) / 64.0);
}

// ---------------------------------------------------------------------------
// helpers
// ---------------------------------------------------------------------------
__device__ __forceinline__ uint32_t smem_u32(const void* p)
{
    uint32_t a;
    asm("{ .reg .u64 t; cvta.to.shared.u64 t, %1; cvt.u32.u64 %0, t; }"
        : "=r"(a) : "l"(p));
    return a;
}
__device__ __forceinline__ void ldsm4(uint32_t* r, uint32_t addr)
{
    asm volatile("ldmatrix.sync.aligned.m8n8.x4.shared.b16 {%0,%1,%2,%3}, [%4];"
                 : "=r"(r[0]), "=r"(r[1]), "=r"(r[2]), "=r"(r[3]) : "r"(addr));
}
__device__ __forceinline__ void mma16816(float* c, const uint32_t* a,
                                         const uint32_t* b)
{
    asm volatile("mma.sync.aligned.m16n8k16.row.col.f32.bf16.bf16.f32 "
                 "{%0,%1,%2,%3}, {%4,%5,%6,%7}, {%8,%9}, {%0,%1,%2,%3};"
                 : "+f"(c[0]), "+f"(c[1]), "+f"(c[2]), "+f"(c[3])
                 : "r"(a[0]), "r"(a[1]), "r"(a[2]), "r"(a[3]),
                   "r"(b[0]), "r"(b[1]));
}
__device__ __forceinline__ void split2(float x, float y, uint32_t& h, uint32_t& l)
{
    __nv_bfloat16 hx = __float2bfloat16(x), hy = __float2bfloat16(y);
    __nv_bfloat16 lx = __float2bfloat16(x - __bfloat162float(hx));
    __nv_bfloat16 ly = __float2bfloat16(y - __bfloat162float(hy));
    __nv_bfloat162 hp{hx, hy}, lp{lx, ly};
    h = *reinterpret_cast<uint32_t*>(&hp);
    l = *reinterpret_cast<uint32_t*>(&lp);
}
__device__ __forceinline__ void cp16(uint32_t dst, const void* src)
{
    asm volatile("cp.async.cg.shared.global [%0], [%1], 16;"
                 :: "r"(dst), "l"(src));
}
__device__ __forceinline__ void cp_commit()
{
    asm volatile("cp.async.commit_group;");
}
__device__ __forceinline__ void cp_wait_n(int n)
{
    if (n == 0)      asm volatile("cp.async.wait_group 0;");
    else if (n == 1) asm volatile("cp.async.wait_group 1;");
    else             asm volatile("cp.async.wait_group 2;");
}
// swizzled byte offset, [rows][32 bf16] (64B rows)
__device__ __forceinline__ uint32_t swz64(int row, int c)
{
    return (uint32_t)(row * 64 + ((c ^ ((row >> 1) & 3)) << 4));
}
// swizzled byte offset, [rows][64 bf16] (128B rows)
__device__ __forceinline__ uint32_t swz128(int row, int c)
{
    return (uint32_t)(row * 128 + ((c ^ (row & 7)) << 4));
}

// ---------------------------------------------------------------------------
// Fused fp32 -> bf16 hi/lo split for all 7 input tensors (one launch).
// ---------------------------------------------------------------------------
__global__ void __launch_bounds__(256)
convert_all(const float* __restrict__ q, const float* __restrict__ k,
            const float* __restrict__ v, const float* __restrict__ Wq,
            const float* __restrict__ Wk, const float* __restrict__ Wv,
            const float* __restrict__ Wo)
{
    const int i = blockIdx.x * blockDim.x + threadIdx.x;
    const float* src;
    __nv_bfloat16 *hi, *lo;
    int off;
    if (i < 3 * NA4) {
        const int which = i >> 20;          // / NA4 (2^20)
        off = i & (NA4 - 1);
        if (which == 0)      { src = q; hi = g_aqH; lo = g_aqL; }
        else if (which == 1) { src = k; hi = g_akH; lo = g_akL; }
        else                 { src = v; hi = g_avH; lo = g_avL; }
    } else {
        const int j = i - 3 * NA4;
        const int which = j >> 18;          // / NW4 (2^18)
        off = j & (NW4 - 1);
        if (which == 0)      { src = Wq; hi = g_wqH; lo = g_wqL; }
        else if (which == 1) { src = Wk; hi = g_wkH; lo = g_wkL; }
        else if (which == 2) { src = Wv; hi = g_wvH; lo = g_wvL; }
        else                 { src = Wo; hi = g_woH; lo = g_woL; }
    }
    float4 val = reinterpret_cast<const float4*>(src)[off];
    uint2 hu, lu;
    split2(val.x, val.y, hu.x, lu.x);
    split2(val.z, val.w, hu.y, lu.y);
    *reinterpret_cast<uint2*>(hi + 4 * (size_t)off) = hu;
    *reinterpret_cast<uint2*>(lo + 4 * (size_t)off) = lu;
}

// ---------------------------------------------------------------------------
// 3-stage cp.async tensor-core GEMM, bf16 hi/lo inputs.
// out = A @ W^T.  BM=BN=128, BK=32, 256 thr, 3-stage smem (96KB), 2 CTAs/SM.
// EPI 0: fp32 [M,E]; EPI 1: RoPE(+scale)+split -> [B,H,S,DH] bf16 pair;
// EPI 2: transpose+split -> [B*H, DH, S] bf16 pair.
// ---------------------------------------------------------------------------
constexpr int GE_STAGE = 32768;   // Ah 0, Al 8192, Bh 16384, Bl 24576
constexpr int GE_SMEM  = 3 * GE_STAGE;
constexpr int GE_NT    = E / 32;  // 32

template <int EPI>
__global__ void __launch_bounds__(256, 2)
gemm_bf(const __nv_bfloat16* __restrict__ Ahg, const __nv_bfloat16* __restrict__ Alg,
        const __nv_bfloat16* __restrict__ Bhg, const __nv_bfloat16* __restrict__ Blg,
        float* __restrict__ outF, __nv_bfloat16* __restrict__ outH,
        __nv_bfloat16* __restrict__ outL, float scale)
{
    extern __shared__ __align__(128) uint8_t smem[];
    const uint32_t sb = smem_u32(smem);

    const int tid  = threadIdx.x;
    const int warp = tid >> 5, lane = tid & 31;
    const int wm = warp & 3;
    const int wn = warp >> 2;
    const int bx = blockIdx.x, by = blockIdx.y;

    const int lr = tid >> 1, lhalf = tid & 1;
    const __nv_bfloat16* pAh = Ahg + (size_t)(by * 128 + lr) * E + lhalf * 16;
    const __nv_bfloat16* pAl = Alg + (size_t)(by * 128 + lr) * E + lhalf * 16;
    const __nv_bfloat16* pBh = Bhg + (size_t)(bx * 128 + lr) * E + lhalf * 16;
    const __nv_bfloat16* pBl = Blg + (size_t)(bx * 128 + lr) * E + lhalf * 16;
    const uint32_t w0 = swz64(lr, lhalf * 2);
    const uint32_t w1 = swz64(lr, lhalf * 2 + 1);

    uint32_t adA[2][2], adB[4][2];
#pragma unroll
    for (int s = 0; s < 2; s++) {
#pragma unroll
        for (int mt = 0; mt < 2; mt++)
            adA[mt][s] = swz64(wm * 32 + mt * 16 + (lane & 15), s * 2 + (lane >> 4));
#pragma unroll
        for (int g = 0; g < 4; g++)
            adB[g][s] = swz64(wn * 64 + g * 16 + ((lane >> 1) & 8) + (lane & 7),
                              s * 2 + ((lane >> 3) & 1));
    }

    float acc[2][8][4];
#pragma unroll
    for (int mt = 0; mt < 2; mt++)
#pragma unroll
        for (int j = 0; j < 8; j++)
#pragma unroll
            for (int r = 0; r < 4; r++) acc[mt][j][r] = 0.f;

    auto load_tile = [&](int t) {
        const uint32_t sg = sb + (t % 3) * GE_STAGE;
        const int kb = t * 32;
        cp16(sg +     0 + w0, pAh + kb);  cp16(sg +     0 + w1, pAh + kb + 8);
        cp16(sg +  8192 + w0, pAl + kb);  cp16(sg +  8192 + w1, pAl + kb + 8);
        cp16(sg + 16384 + w0, pBh + kb);  cp16(sg + 16384 + w1, pBh + kb + 8);
        cp16(sg + 24576 + w0, pBl + kb);  cp16(sg + 24576 + w1, pBl + kb + 8);
        cp_commit();
    };

    load_tile(0);
    load_tile(1);

#pragma unroll 1
    for (int t = 0; t < GE_NT; t++) {
        cp_wait_n(t + 1 < GE_NT ? 1 : 0);   // tile t arrived
        __syncthreads();                    // stage (t+2)%3 reads done too
        if (t + 2 < GE_NT) load_tile(t + 2);
        const uint32_t sg = sb + (t % 3) * GE_STAGE;

#pragma unroll
        for (int s = 0; s < 2; s++) {
            uint32_t fAh[2][4], fAl[2][4], fBh[4][4], fBl[4][4];
#pragma unroll
            for (int mt = 0; mt < 2; mt++) {
                ldsm4(fAh[mt], sg +     0 + adA[mt][s]);
                ldsm4(fAl[mt], sg +  8192 + adA[mt][s]);
            }
#pragma unroll
            for (int g = 0; g < 4; g++) {
                ldsm4(fBh[g], sg + 16384 + adB[g][s]);
                ldsm4(fBl[g], sg + 24576 + adB[g][s]);
            }
#pragma unroll
            for (int mt = 0; mt < 2; mt++)
#pragma unroll
                for (int j = 0; j < 8; j++) {
                    const int g = j >> 1, p = (j & 1) * 2;
                    uint32_t bh[2] = {fBh[g][p], fBh[g][p + 1]};
                    uint32_t bl[2] = {fBl[g][p], fBl[g][p + 1]};
                    mma16816(acc[mt][j], fAh[mt], bh);
                    mma16816(acc[mt][j], fAh[mt], bl);
                    mma16816(acc[mt][j], fAl[mt], bh);
                }
        }
    }

    // ---- epilogues ----
#pragma unroll
    for (int mt = 0; mt < 2; mt++)
#pragma unroll
        for (int j = 0; j < 8; j++) {
            const int m0 = by * 128 + wm * 32 + mt * 16 + (lane >> 2);
            const int n  = bx * 128 + wn * 64 + j * 8 + (lane & 3) * 2;
            if (EPI == 0) {
                *reinterpret_cast<float2*>(outF + (size_t)m0 * E + n) =
                    make_float2(acc[mt][j][0], acc[mt][j][1]);
                *reinterpret_cast<float2*>(outF + (size_t)(m0 + 8) * E + n) =
                    make_float2(acc[mt][j][2], acc[mt][j][3]);
            } else if (EPI == 2) {
                const int hh = (n >> 6) & (H - 1), dd = n & 63;
#pragma unroll
                for (int rr = 0; rr < 2; rr++) {
                    const int m = m0 + rr * 8;
                    const int bb = m >> 11, ss = m & (S - 1);
                    const size_t base = ((size_t)(bb * H + hh) * DH + dd) * S + ss;
                    const float x = acc[mt][j][rr * 2];
                    const float y = acc[mt][j][rr * 2 + 1];
                    __nv_bfloat16 hx = __float2bfloat16(x);
                    __nv_bfloat16 lx = __float2bfloat16(x - __bfloat162float(hx));
                    __nv_bfloat16 hy = __float2bfloat16(y);
                    __nv_bfloat16 ly = __float2bfloat16(y - __bfloat162float(hy));
                    outH[base]     = hx;
                    outL[base]     = lx;
                    outH[base + S] = hy;   // dd+1 row
                    outL[base + S] = ly;
                }
            } else {   // EPI == 1 : RoPE + scale + hi/lo split
                const int hh = (n >> 6) & (H - 1), dd = n & 63;
                const float invf = g_invfreq[dd >> 1];
#pragma unroll
                for (int rr = 0; rr < 2; rr++) {
                    const int m = m0 + rr * 8;
                    const int bb = m >> 11, ss = m & (S - 1);
                    float sn, cs;
                    sincosf((float)ss * invf, &sn, &cs);
                    const float x = acc[mt][j][rr * 2];
                    const float y = acc[mt][j][rr * 2 + 1];
                    const float rx = (x * cs - y * sn) * scale;
                    const float ry = (y * cs + x * sn) * scale;
                    uint32_t h, l;
                    split2(rx, ry, h, l);
                    const size_t off = (((size_t)bb * H + hh) * S + ss) * DH + dd;
                    *reinterpret_cast<uint32_t*>(outH + off) = h;
                    *reinterpret_cast<uint32_t*>(outL + off) = l;
                }
            }
        }
}

// ---------------------------------------------------------------------------
// MMA flash attention, bf16 hi/lo split, 64-key tiles, cp.async double
// buffer.  Grid (S/128, H, B), 256 threads; warp w owns q rows [16w,16w+16).
// smem: Q hi/lo 32KB + 2 stages x (Kh,Kl,Vh,Vl = 32KB) = 96KB -> 2 CTAs/SM.
// Epilogue writes split bf16 activations [B,S,E] for the output projection.
// ---------------------------------------------------------------------------
constexpr int FA_STAGE0 = 32768;   // Qh 0, Ql 16384
constexpr int FA_STAGE  = 32768;   // Kh 0, Kl 8192, Vh 16384, Vl 24576
constexpr int FA_SMEM   = FA_STAGE0 + 2 * FA_STAGE;  // 98304
constexpr int FA_NT     = S / 64;  // 32

__global__ void __launch_bounds__(256, 2)
flash_mma(const __nv_bfloat16* __restrict__ Qh, const __nv_bfloat16* __restrict__ Ql,
          const __nv_bfloat16* __restrict__ Kh, const __nv_bfloat16* __restrict__ Kl,
          const __nv_bfloat16* __restrict__ Vth, const __nv_bfloat16* __restrict__ Vtl,
          __nv_bfloat16* __restrict__ aH, __nv_bfloat16* __restrict__ aL)
{
    extern __shared__ __align__(128) uint8_t sm8[];
    const uint32_t sb = smem_u32(sm8);

    const int tid = threadIdx.x;
    const int warp = tid >> 5, lane = tid & 31;
    const int q0 = blockIdx.x * 128;
    const int hh = blockIdx.y, bb = blockIdx.z;
    const int bh = bb * H + hh;

    // load Q tile hi/lo ([128][64] bf16, swizzled 128B rows)
#pragma unroll
    for (int rep = 0; rep < 4; rep++) {
        const int idx = rep * 256 + tid;
        const int r = idx >> 3, c = idx & 7;
        const size_t go = ((size_t)bh * S + q0 + r) * DH + c * 8;
        const uint32_t so = swz128(r, c);
        *reinterpret_cast<uint4*>(sm8 + so) =
            *reinterpret_cast<const uint4*>(Qh + go);
        *reinterpret_cast<uint4*>(sm8 + 16384 + so) =
            *reinterpret_cast<const uint4*>(Ql + go);
    }

    auto load_tile = [&](int t) {
        const uint32_t sg = sb + FA_STAGE0 + (t & 1) * FA_STAGE;
#pragma unroll
        for (int rep = 0; rep < 2; rep++) {
            const int idx = rep * 256 + tid;
            const int r = idx >> 3, c = idx & 7;
            const uint32_t so = swz128(r, c);
            const size_t gk = ((size_t)bh * S + t * 64 + r) * DH + c * 8;
            cp16(sg + so,        Kh + gk);
            cp16(sg + 8192 + so, Kl + gk);
            const size_t gv = ((size_t)bh * DH + r) * S + t * 64 + c * 8;
            cp16(sg + 16384 + so, Vth + gv);
            cp16(sg + 24576 + so, Vtl + gv);
        }
        cp_commit();
    };

    load_tile(0);

    float m_run[2] = {-1e30f, -1e30f};
    float l_run[2] = {0.f, 0.f};
    float o[8][4];
#pragma unroll
    for (int j = 0; j < 8; j++)
#pragma unroll
        for (int r = 0; r < 4; r++) o[j][r] = 0.f;

    const int aQrow = warp * 16 + (lane & 15);
    const int aQcs  = lane >> 4;
    const int bRow8 = ((lane >> 1) & 8) + (lane & 7);
    const int bCs   = (lane >> 3) & 1;

#pragma unroll 1
    for (int t = 0; t < FA_NT; t++) {
        cp_wait_n(0);        // tile t arrived
        __syncthreads();     // reads of stage (t+1)&1 from iter t-1 done
        if (t + 1 < FA_NT) load_tile(t + 1);
        const uint32_t sg = sb + FA_STAGE0 + (t & 1) * FA_STAGE;

        // ---- S = Q K^T : acc[8 n8-frags][4] ----
        float acc[8][4];
#pragma unroll
        for (int j = 0; j < 8; j++)
#pragma unroll
            for (int r = 0; r < 4; r++) acc[j][r] = 0.f;

#pragma unroll
        for (int s = 0; s < 4; s++) {
            uint32_t ah[4], al[4];
            const uint32_t qoff = swz128(aQrow, 2 * s + aQcs);
            ldsm4(ah, sb + qoff);
            ldsm4(al, sb + 16384 + qoff);
#pragma unroll
            for (int g = 0; g < 4; g++) {
                const uint32_t koff = swz128(g * 16 + bRow8, 2 * s + bCs);
                uint32_t kbh[4], kbl[4];
                ldsm4(kbh, sg + koff);
                ldsm4(kbl, sg + 8192 + koff);
#pragma unroll
                for (int jj = 0; jj < 2; jj++) {
                    const int j = g * 2 + jj, p = jj * 2;
                    uint32_t bH[2] = {kbh[p], kbh[p + 1]};
                    uint32_t bL[2] = {kbl[p], kbl[p + 1]};
                    mma16816(acc[j], ah, bH);
                    mma16816(acc[j], ah, bL);
                    mma16816(acc[j], al, bH);
                }
            }
        }

        // ---- online softmax (quad shuffles) ----
#pragma unroll
        for (int rh = 0; rh < 2; rh++) {
            const int c0 = rh * 2, c1 = rh * 2 + 1;
            float mx = acc[0][c0];
#pragma unroll
            for (int j = 0; j < 8; j++)
                mx = fmaxf(mx, fmaxf(acc[j][c0], acc[j][c1]));
            mx = fmaxf(mx, __shfl_xor_sync(0xffffffffu, mx, 1));
            mx = fmaxf(mx, __shfl_xor_sync(0xffffffffu, mx, 2));
            const float newm = fmaxf(m_run[rh], mx);
            const float corr = __expf(m_run[rh] - newm);
            m_run[rh] = newm;
            float ls = 0.f;
#pragma unroll
            for (int j = 0; j < 8; j++) {
                acc[j][c0] = __expf(acc[j][c0] - newm);
                acc[j][c1] = __expf(acc[j][c1] - newm);
                ls += acc[j][c0] + acc[j][c1];
            }
            ls += __shfl_xor_sync(0xffffffffu, ls, 1);
            ls += __shfl_xor_sync(0xffffffffu, ls, 2);
            l_run[rh] = l_run[rh] * corr + ls;
#pragma unroll
            for (int j = 0; j < 8; j++) {
                o[j][c0] *= corr;
                o[j][c1] *= corr;
            }
        }

        // ---- O += P V : P split in registers, V from swizzled smem ----
#pragma unroll
        for (int s = 0; s < 4; s++) {
            uint32_t pah[4], pal[4];
            split2(acc[2 * s][0], acc[2 * s][1], pah[0], pal[0]);
            split2(acc[2 * s][2], acc[2 * s][3], pah[1], pal[1]);
            split2(acc[2 * s + 1][0], acc[2 * s + 1][1], pah[2], pal[2]);
            split2(acc[2 * s + 1][2], acc[2 * s + 1][3], pah[3], pal[3]);
#pragma unroll
            for (int ng = 0; ng < 4; ng++) {
                const uint32_t voff = swz128(ng * 16 + bRow8, 2 * s + bCs);
                uint32_t vbh[4], vbl[4];
                ldsm4(vbh, sg + 16384 + voff);
                ldsm4(vbl, sg + 24576 + voff);
#pragma unroll
                for (int jj = 0; jj < 2; jj++) {
                    const int j = ng * 2 + jj, p = jj * 2;
                    uint32_t bH[2] = {vbh[p], vbh[p + 1]};
                    uint32_t bL[2] = {vbl[p], vbl[p + 1]};
                    mma16816(o[j], pah, bH);
                    mma16816(o[j], pah, bL);
                    mma16816(o[j], pal, bH);
                }
            }
        }
    }

    // epilogue: normalize, split, write bf16 activations [B,S,E]
    const float inv0 = 1.f / l_run[0];
    const float inv1 = 1.f / l_run[1];
    const int r0 = q0 + warp * 16 + (lane >> 2);
    const int r1 = r0 + 8;
#pragma unroll
    for (int j = 0; j < 8; j++) {
        const int col = hh * 64 + j * 8 + (lane & 3) * 2;
        const size_t off0 = ((size_t)bb * S + r0) * E + col;
        const size_t off1 = ((size_t)bb * S + r1) * E + col;
        uint32_t h, l;
        split2(o[j][0] * inv0, o[j][1] * inv0, h, l);
        *reinterpret_cast<uint32_t*>(aH + off0) = h;
        *reinterpret_cast<uint32_t*>(aL + off0) = l;
        split2(o[j][2] * inv1, o[j][3] * inv1, h, l);
        *reinterpret_cast<uint32_t*>(aH + off1) = h;
        *reinterpret_cast<uint32_t*>(aL + off1) = l;
    }
}

// ---------------------------------------------------------------------------
extern "C" void kernel_launch(void* const* d_in, const int* in_sizes, int n_in,
                              void* d_out, int out_size)
{
    const float* q  = (const float*)d_in[0];
    const float* k  = (const float*)d_in[1];
    const float* v  = (const float*)d_in[2];
    const float* Wq = (const float*)d_in[3];
    const float* Wk = (const float*)d_in[4];
    const float* Wv = (const float*)d_in[5];
    const float* Wo = (const float*)d_in[6];
    float* out = (float*)d_out;

    __nv_bfloat16 *aqH, *aqL, *akH, *akL, *avH, *avL;
    __nv_bfloat16 *wqH, *wqL, *wkH, *wkL, *wvH, *wvL, *woH, *woL;
    __nv_bfloat16 *qh, *ql, *kh, *kl, *vth, *vtl;
    cudaGetSymbolAddress((void**)&aqH, g_aqH);
    cudaGetSymbolAddress((void**)&aqL, g_aqL);
    cudaGetSymbolAddress((void**)&akH, g_akH);
    cudaGetSymbolAddress((void**)&akL, g_akL);
    cudaGetSymbolAddress((void**)&avH, g_avH);
    cudaGetSymbolAddress((void**)&avL, g_avL);
    cudaGetSymbolAddress((void**)&wqH, g_wqH);
    cudaGetSymbolAddress((void**)&wqL, g_wqL);
    cudaGetSymbolAddress((void**)&wkH, g_wkH);
    cudaGetSymbolAddress((void**)&wkL, g_wkL);
    cudaGetSymbolAddress((void**)&wvH, g_wvH);
    cudaGetSymbolAddress((void**)&wvL, g_wvL);
    cudaGetSymbolAddress((void**)&woH, g_woH);
    cudaGetSymbolAddress((void**)&woL, g_woL);
    cudaGetSymbolAddress((void**)&qh,  g_Qh);
    cudaGetSymbolAddress((void**)&ql,  g_Ql);
    cudaGetSymbolAddress((void**)&kh,  g_Kh);
    cudaGetSymbolAddress((void**)&kl,  g_Kl);
    cudaGetSymbolAddress((void**)&vth, g_Vth);
    cudaGetSymbolAddress((void**)&vtl, g_Vtl);

    cudaFuncSetAttribute(gemm_bf<0>,
                         cudaFuncAttributeMaxDynamicSharedMemorySize, GE_SMEM);
    cudaFuncSetAttribute(gemm_bf<1>,
                         cudaFuncAttributeMaxDynamicSharedMemorySize, GE_SMEM);
    cudaFuncSetAttribute(gemm_bf<2>,
                         cudaFuncAttributeMaxDynamicSharedMemorySize, GE_SMEM);
    cudaFuncSetAttribute(flash_mma,
                         cudaFuncAttributeMaxDynamicSharedMemorySize, FA_SMEM);

    init_invfreq_kernel<<<1, 32>>>();

    constexpr int NCONV = (3 * NA4 + 4 * NW4) / 256;   // 16384 blocks
    convert_all<<<NCONV, 256>>>(q, k, v, Wq, Wk, Wv, Wo);

    dim3 gg(E / 128, M_TOT / 128);   // (8, 32)
    gemm_bf<1><<<gg, 256, GE_SMEM>>>(aqH, aqL, wqH, wqL, nullptr, qh, ql, 0.03125f);
    gemm_bf<1><<<gg, 256, GE_SMEM>>>(akH, akL, wkH, wkL, nullptr, kh, kl, 1.0f);
    gemm_bf<2><<<gg, 256, GE_SMEM>>>(avH, avL, wvH, wvL, nullptr, vth, vtl, 0.f);

    dim3 ag(S / 128, H, B);
    flash_mma<<<ag, 256, FA_SMEM>>>(qh, ql, kh, kl, vth, vtl, aqH, aqL);

    gemm_bf<0><<<gg, 256, GE_SMEM>>>(aqH, aqL, woH, woL, out, nullptr, nullptr, 0.f);
}